// round 13
// baseline (speedup 1.0000x reference)
#include <cuda_runtime.h>
#include <math.h>
#include <stdint.h>

#define H128 128
#define NFACT 100000
#define NCOMP 5000
#define NE 500000
#define NBATCH 64
#define DFACT 384
#define DCOMP 64

typedef unsigned long long u64;

// ------------------------- static scratch (device .bss) -------------------------
__device__ float g_xf  [NFACT * H128];
__device__ float g_xf2 [NFACT * H128];
__device__ float g_aggf[NFACT * H128];
__device__ float g_xc  [NCOMP * H128];
__device__ float g_xc2 [NCOMP * H128];
__device__ float g_aggc[NCOMP * H128];
__device__ float g_wf2c[NE];
__device__ float g_wc2f[NE];
__device__ int   g_srcs_f2c[NE];
__device__ float g_ws_f2c  [NE];
__device__ int   g_srcs_c2f[NE];
__device__ float g_ws_c2f  [NE];
__device__ int   g_off_c[NCOMP + 1];
__device__ int   g_off_f[NFACT + 1];
__device__ int   g_cur_c[NCOMP];
__device__ int   g_cur_f[NFACT];
__device__ int   g_cnt_c[NCOMP];
__device__ int   g_cnt_f[NFACT];
__device__ int   g_bsums [256];
__device__ int   g_bsums2[256];
__device__ float g_pool [NBATCH * 256];
__device__ float g_pcnt [2 * NBATCH];
// transposed weights
#define WT_INF_OFF  0
#define WT_INC_OFF  (128 * 384)
#define WT_REL_OFF  (WT_INC_OFF + 128 * 64)
#define WT_ROOT_OFF (WT_REL_OFF + 4 * 128 * 128)
__device__ float g_wt[WT_ROOT_OFF + 4 * 128 * 128];

// ------------------------- f32x2 helpers -------------------------
__device__ __forceinline__ u64 pk2(float a, float b) {
    u64 r; asm("mov.b64 %0, {%1, %2};" : "=l"(r) : "f"(a), "f"(b)); return r;
}
__device__ __forceinline__ void upk2(u64 v, float& a, float& b) {
    asm("mov.b64 {%0, %1}, %2;" : "=f"(a), "=f"(b) : "l"(v));
}
__device__ __forceinline__ u64 fma2(u64 a, u64 b, u64 c) {
    u64 d; asm("fma.rn.f32x2 %0, %1, %2, %3;" : "=l"(d) : "l"(a), "l"(b), "l"(c)); return d;
}
__device__ __forceinline__ u64 relu2(u64 v) {
    float a, b; upk2(v, a, b);
    return pk2(fmaxf(a, 0.f), fmaxf(b, 0.f));
}

// ------------------------- tf32 mma.sync GEMM (M=128, 512 thr, 2-stage, opt LN) --
__device__ __forceinline__ void mma16n8k8(float* c, const uint32_t* a, const uint32_t* b) {
    asm volatile(
        "mma.sync.aligned.m16n8k8.row.col.f32.tf32.tf32.f32 "
        "{%0,%1,%2,%3}, {%4,%5,%6,%7}, {%8,%9}, {%0,%1,%2,%3};"
        : "+f"(c[0]), "+f"(c[1]), "+f"(c[2]), "+f"(c[3])
        : "r"(a[0]), "r"(a[1]), "r"(a[2]), "r"(a[3]), "r"(b[0]), "r"(b[1]));
}
__device__ __forceinline__ uint32_t smem_u32(const void* p) {
    uint32_t a;
    asm("{ .reg .u64 t; cvta.to.shared.u64 t, %1; cvt.u32.u64 %0, t; }" : "=r"(a) : "l"(p));
    return a;
}
__device__ __forceinline__ void cp16(uint32_t dst, const void* src, int sz) {
    asm volatile("cp.async.ca.shared.global [%0], [%1], 16, %2;" :: "r"(dst), "l"(src), "r"(sz));
}
#define CP_COMMIT() asm volatile("cp.async.commit_group;" ::: "memory")
#define CP_WAIT1()  asm volatile("cp.async.wait_group 1;" ::: "memory")
#define CP_WAIT0()  asm volatile("cp.async.wait_group 0;" ::: "memory")

#define TPITCH 36
#define ATILE  (128 * TPITCH)
#define STAGEW (2 * ATILE)
#define GEMM_SMEM_BYTES (2 * STAGEW * 4)   // 73728 B -> 2 CTAs/SM
#define LNPITCH 132

__global__ void __launch_bounds__(512) gemm_mma_k(
    const float* __restrict__ A1, const float* __restrict__ B1t, int K1,
    const float* __restrict__ A2, const float* __restrict__ B2t, int K2,
    const float* __restrict__ bias, const float* __restrict__ prev,
    const float* __restrict__ ln_scale, const float* __restrict__ ln_bias,
    float* __restrict__ C, int M)
{
    extern __shared__ uint32_t sm[];
    const int tid  = threadIdx.x;
    const int lane = tid & 31;
    const int warp = tid >> 5;
    const int wm   = warp & 3;
    const int wn   = warp >> 2;
    const int g    = lane >> 2;
    const int tg   = lane & 3;
    const int m0   = blockIdx.x * 128;
    const uint32_t sbase = smem_u32(sm);

    float acc[2][4][4];
    #pragma unroll
    for (int mf = 0; mf < 2; mf++)
        #pragma unroll
        for (int nf = 0; nf < 4; nf++)
            #pragma unroll
            for (int i = 0; i < 4; i++) acc[mf][nf][i] = 0.f;

    const int nch1 = K1 >> 5;
    const int nch2 = K2 >> 5;
    const int total = nch1 + nch2;

    auto issue_loads = [&](int ch, int stage) {
        const float* A; const float* B; int K, k0;
        if (ch < nch1) { A = A1; B = B1t; K = K1; k0 = ch << 5; }
        else           { A = A2; B = B2t; K = K2; k0 = (ch - nch1) << 5; }
        uint32_t abase = sbase + stage * STAGEW * 4;
        uint32_t bbase = abase + ATILE * 4;
        #pragma unroll
        for (int i = 0; i < 2; i++) {
            int idx = i * 512 + tid;
            int r = idx >> 3, c4 = idx & 7;
            int sz = (m0 + r < M) ? 16 : 0;
            cp16(abase + (r * TPITCH + c4 * 4) * 4,
                 &A[(size_t)(m0 + r < M ? m0 + r : 0) * K + k0 + c4 * 4], sz);
        }
        #pragma unroll
        for (int i = 0; i < 2; i++) {
            int idx = i * 512 + tid;
            int r = idx >> 3, c4 = idx & 7;
            cp16(bbase + (r * TPITCH + c4 * 4) * 4,
                 &B[(size_t)r * K + k0 + c4 * 4], 16);
        }
        CP_COMMIT();
    };

    issue_loads(0, 0);

    for (int ch = 0; ch < total; ch++) {
        const int stage = ch & 1;
        if (ch + 1 < total) {
            issue_loads(ch + 1, stage ^ 1);
            CP_WAIT1();
        } else {
            CP_WAIT0();
        }
        __syncthreads();

        const uint32_t* As = sm + stage * STAGEW;
        const uint32_t* Bs = As + ATILE;

        #pragma unroll
        for (int s = 0; s < 4; s++) {
            const int kk = s * 8;
            uint32_t a[2][4], b[4][2];
            #pragma unroll
            for (int mf = 0; mf < 2; mf++) {
                int rb = wm * 32 + mf * 16;
                a[mf][0] = As[(rb + g    ) * TPITCH + kk + tg    ];
                a[mf][1] = As[(rb + 8 + g) * TPITCH + kk + tg    ];
                a[mf][2] = As[(rb + g    ) * TPITCH + kk + tg + 4];
                a[mf][3] = As[(rb + 8 + g) * TPITCH + kk + tg + 4];
            }
            #pragma unroll
            for (int nf = 0; nf < 4; nf++) {
                int cb = wn * 32 + nf * 8;
                b[nf][0] = Bs[(cb + g) * TPITCH + kk + tg    ];
                b[nf][1] = Bs[(cb + g) * TPITCH + kk + tg + 4];
            }
            #pragma unroll
            for (int mf = 0; mf < 2; mf++)
                #pragma unroll
                for (int nf = 0; nf < 4; nf++)
                    mma16n8k8(acc[mf][nf], a[mf], b[nf]);
        }
        __syncthreads();
    }

    if (ln_scale == nullptr) {
        // plain epilogue: bias + relu (+prev)
        #pragma unroll
        for (int nf = 0; nf < 4; nf++) {
            int col = wn * 32 + nf * 8 + tg * 2;
            float b0 = __ldg(&bias[col]);
            float b1 = __ldg(&bias[col + 1]);
            #pragma unroll
            for (int mf = 0; mf < 2; mf++) {
                int row0 = m0 + wm * 32 + mf * 16 + g;
                if (row0 < M) {
                    float2 o;
                    o.x = fmaxf(acc[mf][nf][0] + b0, 0.f);
                    o.y = fmaxf(acc[mf][nf][1] + b1, 0.f);
                    if (prev) {
                        float2 p = *(const float2*)&prev[(size_t)row0 * 128 + col];
                        o.x += p.x; o.y += p.y;
                    }
                    *(float2*)&C[(size_t)row0 * 128 + col] = o;
                }
                int row1 = row0 + 8;
                if (row1 < M) {
                    float2 o;
                    o.x = fmaxf(acc[mf][nf][2] + b0, 0.f);
                    o.y = fmaxf(acc[mf][nf][3] + b1, 0.f);
                    if (prev) {
                        float2 p = *(const float2*)&prev[(size_t)row1 * 128 + col];
                        o.x += p.x; o.y += p.y;
                    }
                    *(float2*)&C[(size_t)row1 * 128 + col] = o;
                }
            }
        }
        return;
    }

    // fused-LN epilogue: stage relu(acc+bias)+prev in smem, then 4 thr/row LN.
    float* lnb = (float*)sm;   // [128][LNPITCH] = 67584 B, fits in dynamic smem
    __syncthreads();
    #pragma unroll
    for (int nf = 0; nf < 4; nf++) {
        int col = wn * 32 + nf * 8 + tg * 2;
        float b0 = __ldg(&bias[col]);
        float b1 = __ldg(&bias[col + 1]);
        #pragma unroll
        for (int mf = 0; mf < 2; mf++) {
            int r0l = wm * 32 + mf * 16 + g;
            if (m0 + r0l < M) {
                float2 p = *(const float2*)&prev[(size_t)(m0 + r0l) * 128 + col];
                lnb[r0l * LNPITCH + col]     = fmaxf(acc[mf][nf][0] + b0, 0.f) + p.x;
                lnb[r0l * LNPITCH + col + 1] = fmaxf(acc[mf][nf][1] + b1, 0.f) + p.y;
            }
            int r1l = r0l + 8;
            if (m0 + r1l < M) {
                float2 p = *(const float2*)&prev[(size_t)(m0 + r1l) * 128 + col];
                lnb[r1l * LNPITCH + col]     = fmaxf(acc[mf][nf][2] + b0, 0.f) + p.x;
                lnb[r1l * LNPITCH + col + 1] = fmaxf(acc[mf][nf][3] + b1, 0.f) + p.y;
            }
        }
    }
    __syncthreads();

    {
        int row = tid >> 2;        // 0..127
        int q   = tid & 3;         // quarter: cols q*32..q*32+31
        int gr  = m0 + row;
        const float* rp = &lnb[row * LNPITCH + q * 32];
        float s = 0.f, s2 = 0.f;
        #pragma unroll
        for (int i = 0; i < 8; i++) {
            float4 v = *(const float4*)&rp[i * 4];
            s  += v.x + v.y + v.z + v.w;
            s2 += v.x * v.x + v.y * v.y + v.z * v.z + v.w * v.w;
        }
        // reduce across the 4 consecutive lanes holding this row
        s  += __shfl_xor_sync(0xffffffffu, s, 1);
        s2 += __shfl_xor_sync(0xffffffffu, s2, 1);
        s  += __shfl_xor_sync(0xffffffffu, s, 2);
        s2 += __shfl_xor_sync(0xffffffffu, s2, 2);
        float mu  = s * (1.f / 128.f);
        float var = s2 * (1.f / 128.f) - mu * mu;
        float inv = rsqrtf(var + 1e-5f);
        if (gr < M) {
            #pragma unroll
            for (int i = 0; i < 8; i++) {
                int col = q * 32 + i * 4;
                float4 v  = *(const float4*)&rp[i * 4];
                float4 sc = *(const float4*)&ln_scale[col];
                float4 bi = *(const float4*)&ln_bias[col];
                float4 o;
                o.x = (v.x - mu) * inv * sc.x + bi.x;
                o.y = (v.y - mu) * inv * sc.y + bi.y;
                o.z = (v.z - mu) * inv * sc.z + bi.z;
                o.w = (v.w - mu) * inv * sc.w + bi.w;
                *(float4*)&C[(size_t)gr * 128 + col] = o;
            }
        }
    }
}

// ------------------------- weight transpose -------------------------
__global__ void transpose_all_k(const float* __restrict__ W_in_fact,
                                const float* __restrict__ W_in_comp,
                                const float* __restrict__ W_rel,
                                const float* __restrict__ W_root,
                                float* __restrict__ wt)
{
    int i = blockIdx.x * 256 + threadIdx.x;
    int total0 = 384 * 128;
    int total1 = 64 * 128;
    int total2 = 4 * 128 * 128;
    if (i < total0) {
        int k = i >> 7, n = i & 127;
        wt[WT_INF_OFF + n * 384 + k] = W_in_fact[i];
    }
    if (i < total1) {
        int k = i >> 7, n = i & 127;
        wt[WT_INC_OFF + n * 64 + k] = W_in_comp[i];
    }
    if (i < total2) {
        int m = i / 16384, r = i % 16384;
        int k = r >> 7, n = r & 127;
        wt[WT_REL_OFF  + m * 16384 + n * 128 + k] = W_rel[i];
        wt[WT_ROOT_OFF + m * 16384 + n * 128 + k] = W_root[i];
    }
}

// ------------------------- edge gate MLP (f32x2, 2 edges/thread) + hist ----------
__global__ void __launch_bounds__(256) edge_gate_k(
    const float* __restrict__ ea,
    const int* __restrict__ dst, int* __restrict__ cnt,
    const float* __restrict__ eW1, const float* __restrict__ eb1,
    const float* __restrict__ eW2, const float* __restrict__ eb2,
    const float* __restrict__ eW3, const float* __restrict__ eb3,
    float* __restrict__ w)
{
    __shared__ u64 sW1p[11 * 32], sW2p[32 * 16], sW3p[16];
    __shared__ u64 sb1p[32], sb2p[16];
    __shared__ float sb3;
    int tid = threadIdx.x;
    for (int i = tid; i < 11 * 32; i += 256) { float v = eW1[i]; sW1p[i] = pk2(v, v); }
    for (int i = tid; i < 32 * 16; i += 256) { float v = eW2[i]; sW2p[i] = pk2(v, v); }
    if (tid < 32) { float v = eb1[tid]; sb1p[tid] = pk2(v, v); }
    if (tid < 16) {
        float v = eb2[tid]; sb2p[tid] = pk2(v, v);
        float u = eW3[tid]; sW3p[tid] = pk2(u, u);
    }
    if (tid == 0) sb3 = eb3[0];
    __syncthreads();

    int t = blockIdx.x * 256 + tid;
    if (t * 2 >= NE) return;

    // fused dst histogram
    atomicAdd(&cnt[__ldg(&dst[t * 2])], 1);
    atomicAdd(&cnt[__ldg(&dst[t * 2 + 1])], 1);

    float4 v4 = *(const float4*)&ea[(size_t)t * 4];

    u64 xx[11];
    {
        float feat[2][11];
        #pragma unroll
        for (int h = 0; h < 2; h++) {
            float sent  = fminf(fmaxf(h ? v4.z : v4.x, -1.f), 1.f);
            float decay = h ? v4.w : v4.y;
            float dt = fmaxf(-__logf(fmaxf(decay, 1e-6f)) * 100.0f, 0.f);
            float ds = fminf(fmaxf(dt * (1.f / 30.f), 0.f), 12.f);
            float s1, c1;
            sincosf(ds, &s1, &c1);
            float s2 = 2.f * s1 * c1;
            float c2 = 1.f - 2.f * s1 * s1;
            float s3 = s1 * c2 + c1 * s2;
            float c3 = c1 * c2 - s1 * s2;
            float s4 = 2.f * s2 * c2;
            float c4 = 1.f - 2.f * s2 * s2;
            feat[h][0] = sent;
            feat[h][1] = __logf(1.f + dt);
            feat[h][2] = s1; feat[h][3] = s2; feat[h][4] = s3; feat[h][5] = s4;
            feat[h][6] = c1; feat[h][7] = c2; feat[h][8] = c3; feat[h][9] = c4;
            feat[h][10] = ds;
        }
        #pragma unroll
        for (int i = 0; i < 11; i++) xx[i] = pk2(feat[0][i], feat[1][i]);
    }

    u64 h1[32];
    #pragma unroll
    for (int j = 0; j < 32; j++) h1[j] = sb1p[j];
    #pragma unroll
    for (int i = 0; i < 11; i++)
        #pragma unroll
        for (int j = 0; j < 32; j++)
            h1[j] = fma2(xx[i], sW1p[i * 32 + j], h1[j]);
    #pragma unroll
    for (int j = 0; j < 32; j++) h1[j] = relu2(h1[j]);

    u64 zp = pk2(sb3, sb3);
    #pragma unroll
    for (int j = 0; j < 16; j++) {
        u64 a = sb2p[j];
        #pragma unroll
        for (int i = 0; i < 32; i++)
            a = fma2(h1[i], sW2p[i * 16 + j], a);
        zp = fma2(relu2(a), sW3p[j], zp);
    }
    float z0, z1;
    upk2(zp, z0, z1);
    float2 o;
    o.x = 1.f / (1.f + __expf(-z0));
    o.y = 1.f / (1.f + __expf(-z1));
    *(float2*)&w[(size_t)t * 2] = o;
}

// ------------------------- CSR build -------------------------
__global__ void scan_block_k(const int* __restrict__ in, int* __restrict__ out,
                             int* __restrict__ bsums, int n)
{
    __shared__ int s[1024];
    int tid = threadIdx.x;
    int i = blockIdx.x * 1024 + tid;
    int v = (i < n) ? in[i] : 0;
    s[tid] = v;
    __syncthreads();
    for (int o = 1; o < 1024; o <<= 1) {
        int t = 0;
        if (tid >= o) t = s[tid - o];
        __syncthreads();
        if (tid >= o) s[tid] += t;
        __syncthreads();
    }
    if (i < n) out[i] = s[tid] - v;
    if (tid == 1023) bsums[blockIdx.x] = s[1023];
}

__global__ void scan_sums_k(int* __restrict__ bsums, int nb)
{
    __shared__ int s[128];
    int tid = threadIdx.x;
    int v = (tid < nb) ? bsums[tid] : 0;
    s[tid] = v;
    __syncthreads();
    for (int o = 1; o < 128; o <<= 1) {
        int t = 0;
        if (tid >= o) t = s[tid - o];
        __syncthreads();
        if (tid >= o) s[tid] += t;
        __syncthreads();
    }
    if (tid < nb) bsums[tid] = s[tid] - v;
}

__global__ void scan_add_k(int* __restrict__ off, int* __restrict__ cur,
                           const int* __restrict__ bsums, int n, int total)
{
    int i = blockIdx.x * 1024 + threadIdx.x;
    if (i < n) {
        int v = off[i] + bsums[blockIdx.x];
        off[i] = v;
        cur[i] = v;
    }
    if (i == 0) off[n] = total;
}

__global__ void scatter_k(const int* __restrict__ src, const int* __restrict__ dst,
                          const float* __restrict__ w, int* __restrict__ cur,
                          int* __restrict__ srcs_s, float* __restrict__ ws_s, int n)
{
    int e = blockIdx.x * blockDim.x + threadIdx.x;
    if (e >= n) return;
    int d = dst[e];
    int p = atomicAdd(&cur[d], 1);
    srcs_s[p] = src[e];
    ws_s[p]   = w[e];
}

// ------------------------- gather-side aggregation -------------------------
__global__ void aggregate_k(const int* __restrict__ off, const int* __restrict__ srcs,
                            const float* __restrict__ ws, const float* __restrict__ x,
                            float* __restrict__ out, int n)
{
    int node = blockIdx.x * 2 + (threadIdx.x >> 7);
    int c = threadIdx.x & 127;
    if (node >= n) return;
    int s = off[node], e = off[node + 1];
    float acc = 0.f;
    int i = s;
    for (; i + 4 <= e; i += 4) {
        int s0 = __ldg(&srcs[i]);     int s1 = __ldg(&srcs[i + 1]);
        int s2 = __ldg(&srcs[i + 2]); int s3 = __ldg(&srcs[i + 3]);
        float w0 = __ldg(&ws[i]);     float w1 = __ldg(&ws[i + 1]);
        float w2 = __ldg(&ws[i + 2]); float w3 = __ldg(&ws[i + 3]);
        float x0 = __ldg(&x[(size_t)s0 * 128 + c]);
        float x1 = __ldg(&x[(size_t)s1 * 128 + c]);
        float x2 = __ldg(&x[(size_t)s2 * 128 + c]);
        float x3 = __ldg(&x[(size_t)s3 * 128 + c]);
        acc += x0 * w0 + x1 * w1 + x2 * w2 + x3 * w3;
    }
    for (; i < e; i++)
        acc += __ldg(&x[(size_t)__ldg(&srcs[i]) * 128 + c]) * __ldg(&ws[i]);
    out[(size_t)node * 128 + c] = acc;
}

// ------------------------- pooling (sorted-run segment reduction) ----------------
#define PROWS 64
__global__ void pool_seg_k(const float* __restrict__ x, const int* __restrict__ batch,
                           float* __restrict__ pool, float* __restrict__ pcnt,
                           int n, int coloff, int cntoff)
{
    int c = threadIdx.x;
    int r0 = blockIdx.x * PROWS;
    int r1 = r0 + PROWS < n ? r0 + PROWS : n;
    if (r0 >= n) return;
    int curb = __ldg(&batch[r0]);
    float acc = 0.f, cnt = 0.f;
    for (int r = r0; r < r1; r++) {
        int b = __ldg(&batch[r]);
        if (b != curb) {
            atomicAdd(&pool[curb * 256 + coloff + c], acc);
            if (c == 0) atomicAdd(&pcnt[cntoff + curb], cnt);
            acc = 0.f; cnt = 0.f; curb = b;
        }
        acc += x[(size_t)r * 128 + c];
        cnt += 1.f;
    }
    atomicAdd(&pool[curb * 256 + coloff + c], acc);
    if (c == 0) atomicAdd(&pcnt[cntoff + curb], cnt);
}

// ------------------------- classifier (pmean fused) -------------------------
__global__ void classifier_k(const float* __restrict__ pool, const float* __restrict__ pcnt,
                             const float* __restrict__ Wc1, const float* __restrict__ bc1,
                             const float* __restrict__ Wc2, const float* __restrict__ bc2,
                             float* __restrict__ out)
{
    __shared__ float h[64][129];
    __shared__ float invf[64], invc[64];
    int c = threadIdx.x;
    if (c < 64) {
        invf[c] = 1.f / fmaxf(pcnt[c], 1.f);
        invc[c] = 1.f / fmaxf(pcnt[NBATCH + c], 1.f);
    }
    __syncthreads();
    for (int b = 0; b < 64; b++) {
        float a = bc1[c];
        float if_ = invf[b], ic_ = invc[b];
        #pragma unroll 4
        for (int k = 0; k < 128; k++) a += pool[b * 256 + k] * if_ * Wc1[k * 128 + c];
        #pragma unroll 4
        for (int k = 128; k < 256; k++) a += pool[b * 256 + k] * ic_ * Wc1[k * 128 + c];
        h[b][c] = fmaxf(a, 0.f);
    }
    __syncthreads();
    if (c < 64) {
        float a = bc2[0];
        #pragma unroll 4
        for (int k = 0; k < 128; k++) a += h[c][k] * Wc2[k];
        out[c] = a;
    }
}

// ------------------------- host orchestration -------------------------
extern "C" void kernel_launch(void* const* d_in, const int* in_sizes, int n_in,
                              void* d_out, int out_size)
{
    const float* x_fact     = (const float*)d_in[0];
    const float* x_comp     = (const float*)d_in[1];
    const float* ea_f2c     = (const float*)d_in[2];
    const float* ea_c2f     = (const float*)d_in[3];
    const int*   ei_f2c_src = (const int*)d_in[4];
    const int*   ei_f2c_dst = (const int*)d_in[5];
    const int*   ei_c2f_src = (const int*)d_in[6];
    const int*   ei_c2f_dst = (const int*)d_in[7];
    const int*   fact_batch = (const int*)d_in[8];
    const int*   comp_batch = (const int*)d_in[9];
    const float* W_in_fact  = (const float*)d_in[10];
    const float* b_in_fact  = (const float*)d_in[11];
    const float* W_in_comp  = (const float*)d_in[12];
    const float* b_in_comp  = (const float*)d_in[13];
    const float* eW1 = (const float*)d_in[14];
    const float* eb1 = (const float*)d_in[15];
    const float* eW2 = (const float*)d_in[16];
    const float* eb2 = (const float*)d_in[17];
    const float* eW3 = (const float*)d_in[18];
    const float* eb3 = (const float*)d_in[19];
    const float* W_rel    = (const float*)d_in[20];
    const float* b_rel    = (const float*)d_in[21];
    const float* W_root   = (const float*)d_in[22];
    const float* ln_scale = (const float*)d_in[23];
    const float* ln_bias  = (const float*)d_in[24];
    const float* Wc1 = (const float*)d_in[25];
    const float* bc1 = (const float*)d_in[26];
    const float* Wc2 = (const float*)d_in[27];
    const float* bc2 = (const float*)d_in[28];
    float* out = (float*)d_out;

    float *xf, *xf2, *aggf, *xc, *xc2, *aggc, *wf2c, *wc2f;
    float *ws_f2c, *ws_c2f, *pool, *pcnt, *wt;
    int *srcs_f2c, *srcs_c2f, *off_c, *off_f, *cur_c, *cur_f, *cnt_c, *cnt_f;
    int *bsums, *bsums2;
    cudaGetSymbolAddress((void**)&xf,   g_xf);
    cudaGetSymbolAddress((void**)&xf2,  g_xf2);
    cudaGetSymbolAddress((void**)&aggf, g_aggf);
    cudaGetSymbolAddress((void**)&xc,   g_xc);
    cudaGetSymbolAddress((void**)&xc2,  g_xc2);
    cudaGetSymbolAddress((void**)&aggc, g_aggc);
    cudaGetSymbolAddress((void**)&wf2c, g_wf2c);
    cudaGetSymbolAddress((void**)&wc2f, g_wc2f);
    cudaGetSymbolAddress((void**)&srcs_f2c, g_srcs_f2c);
    cudaGetSymbolAddress((void**)&ws_f2c,   g_ws_f2c);
    cudaGetSymbolAddress((void**)&srcs_c2f, g_srcs_c2f);
    cudaGetSymbolAddress((void**)&ws_c2f,   g_ws_c2f);
    cudaGetSymbolAddress((void**)&off_c, g_off_c);
    cudaGetSymbolAddress((void**)&off_f, g_off_f);
    cudaGetSymbolAddress((void**)&cur_c, g_cur_c);
    cudaGetSymbolAddress((void**)&cur_f, g_cur_f);
    cudaGetSymbolAddress((void**)&cnt_c, g_cnt_c);
    cudaGetSymbolAddress((void**)&cnt_f, g_cnt_f);
    cudaGetSymbolAddress((void**)&bsums,  g_bsums);
    cudaGetSymbolAddress((void**)&bsums2, g_bsums2);
    cudaGetSymbolAddress((void**)&pool,  g_pool);
    cudaGetSymbolAddress((void**)&pcnt,  g_pcnt);
    cudaGetSymbolAddress((void**)&wt,    g_wt);

    static cudaStream_t sA = nullptr, sB = nullptr;
    static cudaEvent_t ev[8];
    static int init_done = 0;
    if (!init_done) {
        cudaFuncSetAttribute(gemm_mma_k, cudaFuncAttributeMaxDynamicSharedMemorySize,
                             GEMM_SMEM_BYTES);
        cudaStreamCreateWithFlags(&sA, cudaStreamNonBlocking);
        cudaStreamCreateWithFlags(&sB, cudaStreamNonBlocking);
        for (int i = 0; i < 8; i++) cudaEventCreateWithFlags(&ev[i], cudaEventDisableTiming);
        init_done = 1;
    }

    const int EB = (NE + 255) / 256;
    const int EB2 = (NE / 2 + 255) / 256;
    const int GF = (NFACT + 127) / 128;
    const int GC = (NCOMP + 127) / 128;
    const int nbc = (NCOMP + 1023) / 1024;
    const int nbf = (NFACT + 1023) / 1024;

    cudaMemsetAsync(cnt_c, 0, NCOMP * sizeof(int));
    cudaMemsetAsync(cnt_f, 0, NFACT * sizeof(int));
    cudaMemsetAsync(pool,  0, NBATCH * 256 * sizeof(float));
    cudaMemsetAsync(pcnt,  0, 2 * NBATCH * sizeof(float));

    // fork
    cudaEventRecord(ev[0], 0);
    cudaStreamWaitEvent(sA, ev[0], 0);
    cudaStreamWaitEvent(sB, ev[0], 0);

    // #1 origin: weight transpose
    transpose_all_k<<<256, 256>>>(W_in_fact, W_in_comp, W_rel, W_root, wt);
    // #2 sA, #3 sB: fused gate+hist
    edge_gate_k<<<EB2, 256, 0, sA>>>(ea_f2c, ei_f2c_dst, cnt_c, eW1, eb1, eW2, eb2, eW3, eb3, wf2c);
    edge_gate_k<<<EB2, 256, 0, sB>>>(ea_c2f, ei_c2f_dst, cnt_f, eW1, eb1, eW2, eb2, eW3, eb3, wc2f);
    // #4 origin: fact input GEMM (profiled)
    gemm_mma_k<<<GF, 512, GEMM_SMEM_BYTES>>>(x_fact, wt + WT_INF_OFF, DFACT,
                                             nullptr, nullptr, 0,
                                             b_in_fact, nullptr, nullptr, nullptr, xf, NFACT);

    // sA: f2c CSR (dst = comp)
    scan_block_k<<<nbc, 1024, 0, sA>>>(cnt_c, off_c, bsums, NCOMP);
    scan_sums_k<<<1, 128, 0, sA>>>(bsums, nbc);
    scan_add_k<<<nbc, 1024, 0, sA>>>(off_c, cur_c, bsums, NCOMP, NE);
    scatter_k<<<EB, 256, 0, sA>>>(ei_f2c_src, ei_f2c_dst, wf2c, cur_c, srcs_f2c, ws_f2c, NE);
    cudaEventRecord(ev[1], sA);

    // sB: c2f CSR (dst = fact)
    scan_block_k<<<nbf, 1024, 0, sB>>>(cnt_f, off_f, bsums2, NFACT);
    scan_sums_k<<<1, 128, 0, sB>>>(bsums2, nbf);
    scan_add_k<<<nbf, 1024, 0, sB>>>(off_f, cur_f, bsums2, NFACT, NE);
    scatter_k<<<EB, 256, 0, sB>>>(ei_c2f_src, ei_c2f_dst, wc2f, cur_f, srcs_c2f, ws_c2f, NE);
    cudaEventRecord(ev[2], sB);

    // origin: comp input GEMM
    gemm_mma_k<<<GC, 512, GEMM_SMEM_BYTES>>>(x_comp, wt + WT_INC_OFF, DCOMP,
                                             nullptr, nullptr, 0,
                                             b_in_comp, nullptr, nullptr, nullptr, xc, NCOMP);

    cudaStreamWaitEvent(0, ev[1], 0);
    cudaStreamWaitEvent(0, ev[2], 0);

    float* cf = xf;  float* cc = xc;
    float* nf = xf2; float* nc = xc2;
    for (int l = 0; l < 2; l++) {
        cudaEventRecord(ev[3], 0);
        cudaStreamWaitEvent(sA, ev[3], 0);

        aggregate_k<<<(NCOMP + 1) / 2, 256, 0, sA>>>(off_c, srcs_f2c, ws_f2c, cf, aggc, NCOMP);
        gemm_mma_k<<<GC, 512, GEMM_SMEM_BYTES, sA>>>(aggc, wt + WT_REL_OFF  + (l * 2 + 0) * 16384, 128,
                                                     cc,   wt + WT_ROOT_OFF + (l * 2 + 0) * 16384, 128,
                                                     b_rel + (l * 2 + 0) * 128, cc,
                                                     ln_scale + 128, ln_bias + 128, nc, NCOMP);
        cudaEventRecord(ev[4], sA);

        aggregate_k<<<(NFACT + 1) / 2, 256>>>(off_f, srcs_c2f, ws_c2f, cc, aggf, NFACT);
        gemm_mma_k<<<GF, 512, GEMM_SMEM_BYTES>>>(aggf, wt + WT_REL_OFF  + (l * 2 + 1) * 16384, 128,
                                                 cf,   wt + WT_ROOT_OFF + (l * 2 + 1) * 16384, 128,
                                                 b_rel + (l * 2 + 1) * 128, cf,
                                                 ln_scale, ln_bias, nf, NFACT);

        cudaStreamWaitEvent(0, ev[4], 0);

        float* t;
        t = cf; cf = nf; nf = t;
        t = cc; cc = nc; nc = t;
    }

    cudaEventRecord(ev[5], 0);
    cudaStreamWaitEvent(sA, ev[5], 0);
    pool_seg_k<<<(NCOMP + PROWS - 1) / PROWS, 128, 0, sA>>>(cc, comp_batch, pool, pcnt, NCOMP, 128, NBATCH);
    cudaEventRecord(ev[6], sA);
    pool_seg_k<<<(NFACT + PROWS - 1) / PROWS, 128>>>(cf, fact_batch, pool, pcnt, NFACT, 0, 0);
    cudaStreamWaitEvent(0, ev[6], 0);

    classifier_k<<<1, 128>>>(pool, pcnt, Wc1, bc1, Wc2, bc2, out);
}

// round 14
// speedup vs baseline: 1.0437x; 1.0437x over previous
#include <cuda_runtime.h>
#include <math.h>
#include <stdint.h>

#define H128 128
#define NFACT 100000
#define NCOMP 5000
#define NE 500000
#define NBATCH 64
#define DFACT 384
#define DCOMP 64

typedef unsigned long long u64;

// ------------------------- static scratch (device .bss) -------------------------
__device__ float g_xf  [NFACT * H128];
__device__ float g_xf2 [NFACT * H128];
__device__ float g_aggf[NFACT * H128];
__device__ float g_xc  [NCOMP * H128];
__device__ float g_xc2 [NCOMP * H128];
__device__ float g_aggc[NCOMP * H128];
__device__ float g_wf2c[NE];
__device__ float g_wc2f[NE];
__device__ int   g_srcs_f2c[NE];
__device__ float g_ws_f2c  [NE];
__device__ int   g_srcs_c2f[NE];
__device__ float g_ws_c2f  [NE];
__device__ int   g_off_c[NCOMP + 1];
__device__ int   g_off_f[NFACT + 1];
__device__ int   g_cur_c[NCOMP];
__device__ int   g_cur_f[NFACT];
__device__ int   g_cnt_c[NCOMP];
__device__ int   g_cnt_f[NFACT];
__device__ int   g_bsums [256];
__device__ int   g_bsums2[256];
__device__ float g_pool [NBATCH * 256];
__device__ float g_pcnt [2 * NBATCH];
// transposed weights
#define WT_INF_OFF  0
#define WT_INC_OFF  (128 * 384)
#define WT_REL_OFF  (WT_INC_OFF + 128 * 64)
#define WT_ROOT_OFF (WT_REL_OFF + 4 * 128 * 128)
__device__ float g_wt[WT_ROOT_OFF + 4 * 128 * 128];

// ------------------------- f32x2 helpers -------------------------
__device__ __forceinline__ u64 pk2(float a, float b) {
    u64 r; asm("mov.b64 %0, {%1, %2};" : "=l"(r) : "f"(a), "f"(b)); return r;
}
__device__ __forceinline__ void upk2(u64 v, float& a, float& b) {
    asm("mov.b64 {%0, %1}, %2;" : "=f"(a), "=f"(b) : "l"(v));
}
__device__ __forceinline__ u64 fma2(u64 a, u64 b, u64 c) {
    u64 d; asm("fma.rn.f32x2 %0, %1, %2, %3;" : "=l"(d) : "l"(a), "l"(b), "l"(c)); return d;
}
__device__ __forceinline__ u64 relu2(u64 v) {
    float a, b; upk2(v, a, b);
    return pk2(fmaxf(a, 0.f), fmaxf(b, 0.f));
}

// ------------------------- tf32 mma.sync GEMM (M=128, 512 thr, 2-stage) ---------
__device__ __forceinline__ void mma16n8k8(float* c, const uint32_t* a, const uint32_t* b) {
    asm volatile(
        "mma.sync.aligned.m16n8k8.row.col.f32.tf32.tf32.f32 "
        "{%0,%1,%2,%3}, {%4,%5,%6,%7}, {%8,%9}, {%0,%1,%2,%3};"
        : "+f"(c[0]), "+f"(c[1]), "+f"(c[2]), "+f"(c[3])
        : "r"(a[0]), "r"(a[1]), "r"(a[2]), "r"(a[3]), "r"(b[0]), "r"(b[1]));
}
__device__ __forceinline__ uint32_t smem_u32(const void* p) {
    uint32_t a;
    asm("{ .reg .u64 t; cvta.to.shared.u64 t, %1; cvt.u32.u64 %0, t; }" : "=r"(a) : "l"(p));
    return a;
}
__device__ __forceinline__ void cp16(uint32_t dst, const void* src, int sz) {
    asm volatile("cp.async.ca.shared.global [%0], [%1], 16, %2;" :: "r"(dst), "l"(src), "r"(sz));
}
#define CP_COMMIT() asm volatile("cp.async.commit_group;" ::: "memory")
#define CP_WAIT1()  asm volatile("cp.async.wait_group 1;" ::: "memory")
#define CP_WAIT0()  asm volatile("cp.async.wait_group 0;" ::: "memory")

#define TPITCH 36
#define ATILE  (128 * TPITCH)
#define STAGEW (2 * ATILE)
#define GEMM_SMEM_BYTES (2 * STAGEW * 4)   // 73728 B -> 2 CTAs/SM

__global__ void __launch_bounds__(512) gemm_mma_k(
    const float* __restrict__ A1, const float* __restrict__ B1t, int K1,
    const float* __restrict__ A2, const float* __restrict__ B2t, int K2,
    const float* __restrict__ bias, const float* __restrict__ prev,
    float* __restrict__ C, int M)
{
    extern __shared__ uint32_t sm[];
    const int tid  = threadIdx.x;
    const int lane = tid & 31;
    const int warp = tid >> 5;
    const int wm   = warp & 3;
    const int wn   = warp >> 2;
    const int g    = lane >> 2;
    const int tg   = lane & 3;
    const int m0   = blockIdx.x * 128;
    const uint32_t sbase = smem_u32(sm);

    float acc[2][4][4];
    #pragma unroll
    for (int mf = 0; mf < 2; mf++)
        #pragma unroll
        for (int nf = 0; nf < 4; nf++)
            #pragma unroll
            for (int i = 0; i < 4; i++) acc[mf][nf][i] = 0.f;

    const int nch1 = K1 >> 5;
    const int nch2 = K2 >> 5;
    const int total = nch1 + nch2;

    auto issue_loads = [&](int ch, int stage) {
        const float* A; const float* B; int K, k0;
        if (ch < nch1) { A = A1; B = B1t; K = K1; k0 = ch << 5; }
        else           { A = A2; B = B2t; K = K2; k0 = (ch - nch1) << 5; }
        uint32_t abase = sbase + stage * STAGEW * 4;
        uint32_t bbase = abase + ATILE * 4;
        #pragma unroll
        for (int i = 0; i < 2; i++) {
            int idx = i * 512 + tid;
            int r = idx >> 3, c4 = idx & 7;
            int sz = (m0 + r < M) ? 16 : 0;
            cp16(abase + (r * TPITCH + c4 * 4) * 4,
                 &A[(size_t)(m0 + r < M ? m0 + r : 0) * K + k0 + c4 * 4], sz);
        }
        #pragma unroll
        for (int i = 0; i < 2; i++) {
            int idx = i * 512 + tid;
            int r = idx >> 3, c4 = idx & 7;
            cp16(bbase + (r * TPITCH + c4 * 4) * 4,
                 &B[(size_t)r * K + k0 + c4 * 4], 16);
        }
        CP_COMMIT();
    };

    issue_loads(0, 0);

    for (int ch = 0; ch < total; ch++) {
        const int stage = ch & 1;
        if (ch + 1 < total) {
            issue_loads(ch + 1, stage ^ 1);
            CP_WAIT1();
        } else {
            CP_WAIT0();
        }
        __syncthreads();

        const uint32_t* As = sm + stage * STAGEW;
        const uint32_t* Bs = As + ATILE;

        #pragma unroll
        for (int s = 0; s < 4; s++) {
            const int kk = s * 8;
            uint32_t a[2][4], b[4][2];
            #pragma unroll
            for (int mf = 0; mf < 2; mf++) {
                int rb = wm * 32 + mf * 16;
                a[mf][0] = As[(rb + g    ) * TPITCH + kk + tg    ];
                a[mf][1] = As[(rb + 8 + g) * TPITCH + kk + tg    ];
                a[mf][2] = As[(rb + g    ) * TPITCH + kk + tg + 4];
                a[mf][3] = As[(rb + 8 + g) * TPITCH + kk + tg + 4];
            }
            #pragma unroll
            for (int nf = 0; nf < 4; nf++) {
                int cb = wn * 32 + nf * 8;
                b[nf][0] = Bs[(cb + g) * TPITCH + kk + tg    ];
                b[nf][1] = Bs[(cb + g) * TPITCH + kk + tg + 4];
            }
            #pragma unroll
            for (int mf = 0; mf < 2; mf++)
                #pragma unroll
                for (int nf = 0; nf < 4; nf++)
                    mma16n8k8(acc[mf][nf], a[mf], b[nf]);
        }
        __syncthreads();
    }

    #pragma unroll
    for (int nf = 0; nf < 4; nf++) {
        int col = wn * 32 + nf * 8 + tg * 2;
        float b0 = __ldg(&bias[col]);
        float b1 = __ldg(&bias[col + 1]);
        #pragma unroll
        for (int mf = 0; mf < 2; mf++) {
            int row0 = m0 + wm * 32 + mf * 16 + g;
            if (row0 < M) {
                float2 o;
                o.x = fmaxf(acc[mf][nf][0] + b0, 0.f);
                o.y = fmaxf(acc[mf][nf][1] + b1, 0.f);
                if (prev) {
                    float2 p = *(const float2*)&prev[(size_t)row0 * 128 + col];
                    o.x += p.x; o.y += p.y;
                }
                *(float2*)&C[(size_t)row0 * 128 + col] = o;
            }
            int row1 = row0 + 8;
            if (row1 < M) {
                float2 o;
                o.x = fmaxf(acc[mf][nf][2] + b0, 0.f);
                o.y = fmaxf(acc[mf][nf][3] + b1, 0.f);
                if (prev) {
                    float2 p = *(const float2*)&prev[(size_t)row1 * 128 + col];
                    o.x += p.x; o.y += p.y;
                }
                *(float2*)&C[(size_t)row1 * 128 + col] = o;
            }
        }
    }
}

// ------------------------- weight transpose -------------------------
__global__ void transpose_all_k(const float* __restrict__ W_in_fact,
                                const float* __restrict__ W_in_comp,
                                const float* __restrict__ W_rel,
                                const float* __restrict__ W_root,
                                float* __restrict__ wt)
{
    int i = blockIdx.x * 256 + threadIdx.x;
    int total0 = 384 * 128;
    int total1 = 64 * 128;
    int total2 = 4 * 128 * 128;
    if (i < total0) {
        int k = i >> 7, n = i & 127;
        wt[WT_INF_OFF + n * 384 + k] = W_in_fact[i];
    }
    if (i < total1) {
        int k = i >> 7, n = i & 127;
        wt[WT_INC_OFF + n * 64 + k] = W_in_comp[i];
    }
    if (i < total2) {
        int m = i / 16384, r = i % 16384;
        int k = r >> 7, n = r & 127;
        wt[WT_REL_OFF  + m * 16384 + n * 128 + k] = W_rel[i];
        wt[WT_ROOT_OFF + m * 16384 + n * 128 + k] = W_root[i];
    }
}

// ------------------------- edge gate MLP (f32x2, 2 edges/thread) + hist ----------
__global__ void __launch_bounds__(256) edge_gate_k(
    const float* __restrict__ ea,
    const int* __restrict__ dst, int* __restrict__ cnt,
    const float* __restrict__ eW1, const float* __restrict__ eb1,
    const float* __restrict__ eW2, const float* __restrict__ eb2,
    const float* __restrict__ eW3, const float* __restrict__ eb3,
    float* __restrict__ w)
{
    __shared__ u64 sW1p[11 * 32], sW2p[32 * 16], sW3p[16];
    __shared__ u64 sb1p[32], sb2p[16];
    __shared__ float sb3;
    int tid = threadIdx.x;
    for (int i = tid; i < 11 * 32; i += 256) { float v = eW1[i]; sW1p[i] = pk2(v, v); }
    for (int i = tid; i < 32 * 16; i += 256) { float v = eW2[i]; sW2p[i] = pk2(v, v); }
    if (tid < 32) { float v = eb1[tid]; sb1p[tid] = pk2(v, v); }
    if (tid < 16) {
        float v = eb2[tid]; sb2p[tid] = pk2(v, v);
        float u = eW3[tid]; sW3p[tid] = pk2(u, u);
    }
    if (tid == 0) sb3 = eb3[0];
    __syncthreads();

    int t = blockIdx.x * 256 + tid;
    if (t * 2 >= NE) return;

    // fused dst histogram
    atomicAdd(&cnt[__ldg(&dst[t * 2])], 1);
    atomicAdd(&cnt[__ldg(&dst[t * 2 + 1])], 1);

    float4 v4 = *(const float4*)&ea[(size_t)t * 4];

    u64 xx[11];
    {
        float feat[2][11];
        #pragma unroll
        for (int h = 0; h < 2; h++) {
            float sent  = fminf(fmaxf(h ? v4.z : v4.x, -1.f), 1.f);
            float decay = h ? v4.w : v4.y;
            float dt = fmaxf(-__logf(fmaxf(decay, 1e-6f)) * 100.0f, 0.f);
            float ds = fminf(fmaxf(dt * (1.f / 30.f), 0.f), 12.f);
            float s1, c1;
            sincosf(ds, &s1, &c1);
            float s2 = 2.f * s1 * c1;
            float c2 = 1.f - 2.f * s1 * s1;
            float s3 = s1 * c2 + c1 * s2;
            float c3 = c1 * c2 - s1 * s2;
            float s4 = 2.f * s2 * c2;
            float c4 = 1.f - 2.f * s2 * s2;
            feat[h][0] = sent;
            feat[h][1] = __logf(1.f + dt);
            feat[h][2] = s1; feat[h][3] = s2; feat[h][4] = s3; feat[h][5] = s4;
            feat[h][6] = c1; feat[h][7] = c2; feat[h][8] = c3; feat[h][9] = c4;
            feat[h][10] = ds;
        }
        #pragma unroll
        for (int i = 0; i < 11; i++) xx[i] = pk2(feat[0][i], feat[1][i]);
    }

    u64 h1[32];
    #pragma unroll
    for (int j = 0; j < 32; j++) h1[j] = sb1p[j];
    #pragma unroll
    for (int i = 0; i < 11; i++)
        #pragma unroll
        for (int j = 0; j < 32; j++)
            h1[j] = fma2(xx[i], sW1p[i * 32 + j], h1[j]);
    #pragma unroll
    for (int j = 0; j < 32; j++) h1[j] = relu2(h1[j]);

    u64 zp = pk2(sb3, sb3);
    #pragma unroll
    for (int j = 0; j < 16; j++) {
        u64 a = sb2p[j];
        #pragma unroll
        for (int i = 0; i < 32; i++)
            a = fma2(h1[i], sW2p[i * 16 + j], a);
        zp = fma2(relu2(a), sW3p[j], zp);
    }
    float z0, z1;
    upk2(zp, z0, z1);
    float2 o;
    o.x = 1.f / (1.f + __expf(-z0));
    o.y = 1.f / (1.f + __expf(-z1));
    *(float2*)&w[(size_t)t * 2] = o;
}

// ------------------------- CSR build -------------------------
__global__ void scan_block_k(const int* __restrict__ in, int* __restrict__ out,
                             int* __restrict__ bsums, int n)
{
    __shared__ int s[1024];
    int tid = threadIdx.x;
    int i = blockIdx.x * 1024 + tid;
    int v = (i < n) ? in[i] : 0;
    s[tid] = v;
    __syncthreads();
    for (int o = 1; o < 1024; o <<= 1) {
        int t = 0;
        if (tid >= o) t = s[tid - o];
        __syncthreads();
        if (tid >= o) s[tid] += t;
        __syncthreads();
    }
    if (i < n) out[i] = s[tid] - v;
    if (tid == 1023) bsums[blockIdx.x] = s[1023];
}

__global__ void scan_sums_k(int* __restrict__ bsums, int nb)
{
    __shared__ int s[128];
    int tid = threadIdx.x;
    int v = (tid < nb) ? bsums[tid] : 0;
    s[tid] = v;
    __syncthreads();
    for (int o = 1; o < 128; o <<= 1) {
        int t = 0;
        if (tid >= o) t = s[tid - o];
        __syncthreads();
        if (tid >= o) s[tid] += t;
        __syncthreads();
    }
    if (tid < nb) bsums[tid] = s[tid] - v;
}

__global__ void scan_add_k(int* __restrict__ off, int* __restrict__ cur,
                           const int* __restrict__ bsums, int n, int total)
{
    int i = blockIdx.x * 1024 + threadIdx.x;
    if (i < n) {
        int v = off[i] + bsums[blockIdx.x];
        off[i] = v;
        cur[i] = v;
    }
    if (i == 0) off[n] = total;
}

__global__ void scatter_k(const int* __restrict__ src, const int* __restrict__ dst,
                          const float* __restrict__ w, int* __restrict__ cur,
                          int* __restrict__ srcs_s, float* __restrict__ ws_s, int n)
{
    int e = blockIdx.x * blockDim.x + threadIdx.x;
    if (e >= n) return;
    int d = dst[e];
    int p = atomicAdd(&cur[d], 1);
    srcs_s[p] = src[e];
    ws_s[p]   = w[e];
}

// ------------------------- gather-side aggregation -------------------------
__global__ void aggregate_k(const int* __restrict__ off, const int* __restrict__ srcs,
                            const float* __restrict__ ws, const float* __restrict__ x,
                            float* __restrict__ out, int n)
{
    int node = blockIdx.x * 2 + (threadIdx.x >> 7);
    int c = threadIdx.x & 127;
    if (node >= n) return;
    int s = off[node], e = off[node + 1];
    float acc = 0.f;
    int i = s;
    for (; i + 4 <= e; i += 4) {
        int s0 = __ldg(&srcs[i]);     int s1 = __ldg(&srcs[i + 1]);
        int s2 = __ldg(&srcs[i + 2]); int s3 = __ldg(&srcs[i + 3]);
        float w0 = __ldg(&ws[i]);     float w1 = __ldg(&ws[i + 1]);
        float w2 = __ldg(&ws[i + 2]); float w3 = __ldg(&ws[i + 3]);
        float x0 = __ldg(&x[(size_t)s0 * 128 + c]);
        float x1 = __ldg(&x[(size_t)s1 * 128 + c]);
        float x2 = __ldg(&x[(size_t)s2 * 128 + c]);
        float x3 = __ldg(&x[(size_t)s3 * 128 + c]);
        acc += x0 * w0 + x1 * w1 + x2 * w2 + x3 * w3;
    }
    for (; i < e; i++)
        acc += __ldg(&x[(size_t)__ldg(&srcs[i]) * 128 + c]) * __ldg(&ws[i]);
    out[(size_t)node * 128 + c] = acc;
}

// ------------------------- layernorm (8 rows/block, 1 warp/row) -------------------------
__global__ void layernorm_k(float* __restrict__ x, const float* __restrict__ scale,
                            const float* __restrict__ bias, int n)
{
    int warp = threadIdx.x >> 5;
    int lane = threadIdx.x & 31;
    int row = blockIdx.x * 8 + warp;
    if (row >= n) return;
    float4 v = *(const float4*)&x[(size_t)row * 128 + lane * 4];
    float s  = v.x + v.y + v.z + v.w;
    float s2 = v.x * v.x + v.y * v.y + v.z * v.z + v.w * v.w;
    #pragma unroll
    for (int o = 16; o > 0; o >>= 1) {
        s  += __shfl_xor_sync(0xffffffffu, s, o);
        s2 += __shfl_xor_sync(0xffffffffu, s2, o);
    }
    float mu  = s * (1.f / 128.f);
    float var = s2 * (1.f / 128.f) - mu * mu;
    float inv = rsqrtf(var + 1e-5f);
    float4 sc = *(const float4*)&scale[lane * 4];
    float4 bi = *(const float4*)&bias[lane * 4];
    float4 o;
    o.x = (v.x - mu) * inv * sc.x + bi.x;
    o.y = (v.y - mu) * inv * sc.y + bi.y;
    o.z = (v.z - mu) * inv * sc.z + bi.z;
    o.w = (v.w - mu) * inv * sc.w + bi.w;
    *(float4*)&x[(size_t)row * 128 + lane * 4] = o;
}

// ------------------------- pooling (sorted-run segment reduction) ----------------
#define PROWS 64
__global__ void pool_seg_k(const float* __restrict__ x, const int* __restrict__ batch,
                           float* __restrict__ pool, float* __restrict__ pcnt,
                           int n, int coloff, int cntoff)
{
    int c = threadIdx.x;
    int r0 = blockIdx.x * PROWS;
    int r1 = r0 + PROWS < n ? r0 + PROWS : n;
    if (r0 >= n) return;
    int curb = __ldg(&batch[r0]);
    float acc = 0.f, cnt = 0.f;
    for (int r = r0; r < r1; r++) {
        int b = __ldg(&batch[r]);
        if (b != curb) {
            atomicAdd(&pool[curb * 256 + coloff + c], acc);
            if (c == 0) atomicAdd(&pcnt[cntoff + curb], cnt);
            acc = 0.f; cnt = 0.f; curb = b;
        }
        acc += x[(size_t)r * 128 + c];
        cnt += 1.f;
    }
    atomicAdd(&pool[curb * 256 + coloff + c], acc);
    if (c == 0) atomicAdd(&pcnt[cntoff + curb], cnt);
}

// ------------------------- classifier (pmean fused) -------------------------
__global__ void classifier_k(const float* __restrict__ pool, const float* __restrict__ pcnt,
                             const float* __restrict__ Wc1, const float* __restrict__ bc1,
                             const float* __restrict__ Wc2, const float* __restrict__ bc2,
                             float* __restrict__ out)
{
    __shared__ float h[64][129];
    __shared__ float invf[64], invc[64];
    int c = threadIdx.x;
    if (c < 64) {
        invf[c] = 1.f / fmaxf(pcnt[c], 1.f);
        invc[c] = 1.f / fmaxf(pcnt[NBATCH + c], 1.f);
    }
    __syncthreads();
    for (int b = 0; b < 64; b++) {
        float a = bc1[c];
        float if_ = invf[b], ic_ = invc[b];
        #pragma unroll 4
        for (int k = 0; k < 128; k++) a += pool[b * 256 + k] * if_ * Wc1[k * 128 + c];
        #pragma unroll 4
        for (int k = 128; k < 256; k++) a += pool[b * 256 + k] * ic_ * Wc1[k * 128 + c];
        h[b][c] = fmaxf(a, 0.f);
    }
    __syncthreads();
    if (c < 64) {
        float a = bc2[0];
        #pragma unroll 4
        for (int k = 0; k < 128; k++) a += h[c][k] * Wc2[k];
        out[c] = a;
    }
}

// ------------------------- host orchestration -------------------------
extern "C" void kernel_launch(void* const* d_in, const int* in_sizes, int n_in,
                              void* d_out, int out_size)
{
    const float* x_fact     = (const float*)d_in[0];
    const float* x_comp     = (const float*)d_in[1];
    const float* ea_f2c     = (const float*)d_in[2];
    const float* ea_c2f     = (const float*)d_in[3];
    const int*   ei_f2c_src = (const int*)d_in[4];
    const int*   ei_f2c_dst = (const int*)d_in[5];
    const int*   ei_c2f_src = (const int*)d_in[6];
    const int*   ei_c2f_dst = (const int*)d_in[7];
    const int*   fact_batch = (const int*)d_in[8];
    const int*   comp_batch = (const int*)d_in[9];
    const float* W_in_fact  = (const float*)d_in[10];
    const float* b_in_fact  = (const float*)d_in[11];
    const float* W_in_comp  = (const float*)d_in[12];
    const float* b_in_comp  = (const float*)d_in[13];
    const float* eW1 = (const float*)d_in[14];
    const float* eb1 = (const float*)d_in[15];
    const float* eW2 = (const float*)d_in[16];
    const float* eb2 = (const float*)d_in[17];
    const float* eW3 = (const float*)d_in[18];
    const float* eb3 = (const float*)d_in[19];
    const float* W_rel    = (const float*)d_in[20];
    const float* b_rel    = (const float*)d_in[21];
    const float* W_root   = (const float*)d_in[22];
    const float* ln_scale = (const float*)d_in[23];
    const float* ln_bias  = (const float*)d_in[24];
    const float* Wc1 = (const float*)d_in[25];
    const float* bc1 = (const float*)d_in[26];
    const float* Wc2 = (const float*)d_in[27];
    const float* bc2 = (const float*)d_in[28];
    float* out = (float*)d_out;

    float *xf, *xf2, *aggf, *xc, *xc2, *aggc, *wf2c, *wc2f;
    float *ws_f2c, *ws_c2f, *pool, *pcnt, *wt;
    int *srcs_f2c, *srcs_c2f, *off_c, *off_f, *cur_c, *cur_f, *cnt_c, *cnt_f;
    int *bsums, *bsums2;
    cudaGetSymbolAddress((void**)&xf,   g_xf);
    cudaGetSymbolAddress((void**)&xf2,  g_xf2);
    cudaGetSymbolAddress((void**)&aggf, g_aggf);
    cudaGetSymbolAddress((void**)&xc,   g_xc);
    cudaGetSymbolAddress((void**)&xc2,  g_xc2);
    cudaGetSymbolAddress((void**)&aggc, g_aggc);
    cudaGetSymbolAddress((void**)&wf2c, g_wf2c);
    cudaGetSymbolAddress((void**)&wc2f, g_wc2f);
    cudaGetSymbolAddress((void**)&srcs_f2c, g_srcs_f2c);
    cudaGetSymbolAddress((void**)&ws_f2c,   g_ws_f2c);
    cudaGetSymbolAddress((void**)&srcs_c2f, g_srcs_c2f);
    cudaGetSymbolAddress((void**)&ws_c2f,   g_ws_c2f);
    cudaGetSymbolAddress((void**)&off_c, g_off_c);
    cudaGetSymbolAddress((void**)&off_f, g_off_f);
    cudaGetSymbolAddress((void**)&cur_c, g_cur_c);
    cudaGetSymbolAddress((void**)&cur_f, g_cur_f);
    cudaGetSymbolAddress((void**)&cnt_c, g_cnt_c);
    cudaGetSymbolAddress((void**)&cnt_f, g_cnt_f);
    cudaGetSymbolAddress((void**)&bsums,  g_bsums);
    cudaGetSymbolAddress((void**)&bsums2, g_bsums2);
    cudaGetSymbolAddress((void**)&pool,  g_pool);
    cudaGetSymbolAddress((void**)&pcnt,  g_pcnt);
    cudaGetSymbolAddress((void**)&wt,    g_wt);

    static cudaStream_t sA = nullptr, sB = nullptr;
    static cudaEvent_t ev[8];
    static int init_done = 0;
    if (!init_done) {
        cudaFuncSetAttribute(gemm_mma_k, cudaFuncAttributeMaxDynamicSharedMemorySize,
                             GEMM_SMEM_BYTES);
        cudaStreamCreateWithFlags(&sA, cudaStreamNonBlocking);
        cudaStreamCreateWithFlags(&sB, cudaStreamNonBlocking);
        for (int i = 0; i < 8; i++) cudaEventCreateWithFlags(&ev[i], cudaEventDisableTiming);
        init_done = 1;
    }

    const int EB = (NE + 255) / 256;
    const int EB2 = (NE / 2 + 255) / 256;
    const int GF = (NFACT + 127) / 128;
    const int GC = (NCOMP + 127) / 128;
    const int nbc = (NCOMP + 1023) / 1024;
    const int nbf = (NFACT + 1023) / 1024;

    cudaMemsetAsync(cnt_c, 0, NCOMP * sizeof(int));
    cudaMemsetAsync(cnt_f, 0, NFACT * sizeof(int));
    cudaMemsetAsync(pool,  0, NBATCH * 256 * sizeof(float));
    cudaMemsetAsync(pcnt,  0, 2 * NBATCH * sizeof(float));

    // fork
    cudaEventRecord(ev[0], 0);
    cudaStreamWaitEvent(sA, ev[0], 0);
    cudaStreamWaitEvent(sB, ev[0], 0);

    // #1 origin: weight transpose
    transpose_all_k<<<256, 256>>>(W_in_fact, W_in_comp, W_rel, W_root, wt);
    // #2 sA, #3 sB: fused gate+hist
    edge_gate_k<<<EB2, 256, 0, sA>>>(ea_f2c, ei_f2c_dst, cnt_c, eW1, eb1, eW2, eb2, eW3, eb3, wf2c);
    edge_gate_k<<<EB2, 256, 0, sB>>>(ea_c2f, ei_c2f_dst, cnt_f, eW1, eb1, eW2, eb2, eW3, eb3, wc2f);
    // #4 origin: fact input GEMM (profiled)
    gemm_mma_k<<<GF, 512, GEMM_SMEM_BYTES>>>(x_fact, wt + WT_INF_OFF, DFACT,
                                             nullptr, nullptr, 0,
                                             b_in_fact, nullptr, xf, NFACT);

    // sA: f2c CSR (dst = comp)
    scan_block_k<<<nbc, 1024, 0, sA>>>(cnt_c, off_c, bsums, NCOMP);
    scan_sums_k<<<1, 128, 0, sA>>>(bsums, nbc);
    scan_add_k<<<nbc, 1024, 0, sA>>>(off_c, cur_c, bsums, NCOMP, NE);
    scatter_k<<<EB, 256, 0, sA>>>(ei_f2c_src, ei_f2c_dst, wf2c, cur_c, srcs_f2c, ws_f2c, NE);
    cudaEventRecord(ev[1], sA);

    // sB: c2f CSR (dst = fact)
    scan_block_k<<<nbf, 1024, 0, sB>>>(cnt_f, off_f, bsums2, NFACT);
    scan_sums_k<<<1, 128, 0, sB>>>(bsums2, nbf);
    scan_add_k<<<nbf, 1024, 0, sB>>>(off_f, cur_f, bsums2, NFACT, NE);
    scatter_k<<<EB, 256, 0, sB>>>(ei_c2f_src, ei_c2f_dst, wc2f, cur_f, srcs_c2f, ws_c2f, NE);
    cudaEventRecord(ev[2], sB);

    // origin: comp input GEMM
    gemm_mma_k<<<GC, 512, GEMM_SMEM_BYTES>>>(x_comp, wt + WT_INC_OFF, DCOMP,
                                             nullptr, nullptr, 0,
                                             b_in_comp, nullptr, xc, NCOMP);

    cudaStreamWaitEvent(0, ev[1], 0);
    cudaStreamWaitEvent(0, ev[2], 0);

    float* cf = xf;  float* cc = xc;
    float* nf = xf2; float* nc = xc2;
    for (int l = 0; l < 2; l++) {
        cudaEventRecord(ev[3], 0);
        cudaStreamWaitEvent(sA, ev[3], 0);

        aggregate_k<<<(NCOMP + 1) / 2, 256, 0, sA>>>(off_c, srcs_f2c, ws_f2c, cf, aggc, NCOMP);
        gemm_mma_k<<<GC, 512, GEMM_SMEM_BYTES, sA>>>(aggc, wt + WT_REL_OFF  + (l * 2 + 0) * 16384, 128,
                                                     cc,   wt + WT_ROOT_OFF + (l * 2 + 0) * 16384, 128,
                                                     b_rel + (l * 2 + 0) * 128, cc, nc, NCOMP);
        layernorm_k<<<(NCOMP + 7) / 8, 256, 0, sA>>>(nc, ln_scale + 128, ln_bias + 128, NCOMP);
        cudaEventRecord(ev[4], sA);

        aggregate_k<<<(NFACT + 1) / 2, 256>>>(off_f, srcs_c2f, ws_c2f, cc, aggf, NFACT);
        gemm_mma_k<<<GF, 512, GEMM_SMEM_BYTES>>>(aggf, wt + WT_REL_OFF  + (l * 2 + 1) * 16384, 128,
                                                 cf,   wt + WT_ROOT_OFF + (l * 2 + 1) * 16384, 128,
                                                 b_rel + (l * 2 + 1) * 128, cf, nf, NFACT);
        layernorm_k<<<(NFACT + 7) / 8, 256>>>(nf, ln_scale, ln_bias, NFACT);

        cudaStreamWaitEvent(0, ev[4], 0);

        float* t;
        t = cf; cf = nf; nf = t;
        t = cc; cc = nc; nc = t;
    }

    cudaEventRecord(ev[5], 0);
    cudaStreamWaitEvent(sA, ev[5], 0);
    pool_seg_k<<<(NCOMP + PROWS - 1) / PROWS, 128, 0, sA>>>(cc, comp_batch, pool, pcnt, NCOMP, 128, NBATCH);
    cudaEventRecord(ev[6], sA);
    pool_seg_k<<<(NFACT + PROWS - 1) / PROWS, 128>>>(cf, fact_batch, pool, pcnt, NFACT, 0, 0);
    cudaStreamWaitEvent(0, ev[6], 0);

    classifier_k<<<1, 128>>>(pool, pcnt, Wc1, bc1, Wc2, bc2, out);
}

// round 15
// speedup vs baseline: 1.0487x; 1.0048x over previous
#include <cuda_runtime.h>
#include <math.h>
#include <stdint.h>

#define H128 128
#define NFACT 100000
#define NCOMP 5000
#define NE 500000
#define NBATCH 64
#define DFACT 384
#define DCOMP 64

typedef unsigned long long u64;

// ------------------------- static scratch (device .bss) -------------------------
__device__ float g_xf  [NFACT * H128];
__device__ float g_xf2 [NFACT * H128];
__device__ float g_aggf[NFACT * H128];
__device__ float g_xc  [NCOMP * H128];
__device__ float g_xc2 [NCOMP * H128];
__device__ float g_aggc[NCOMP * H128];
__device__ float g_wf2c[NE];
__device__ float g_wc2f[NE];
__device__ int   g_srcs_f2c[NE];
__device__ float g_ws_f2c  [NE];
__device__ int   g_srcs_c2f[NE];
__device__ float g_ws_c2f  [NE];
__device__ int   g_off_c[NCOMP + 1];
__device__ int   g_off_f[NFACT + 1];
__device__ int   g_cur_c[NCOMP];
__device__ int   g_cur_f[NFACT];
__device__ int   g_cnt_c[NCOMP];
__device__ int   g_cnt_f[NFACT];
__device__ int   g_bsums [256];
__device__ int   g_bsums2[256];
__device__ float g_pool [NBATCH * 256];
__device__ float g_pcnt [2 * NBATCH];
// transposed weights
#define WT_INF_OFF  0
#define WT_INC_OFF  (128 * 384)
#define WT_REL_OFF  (WT_INC_OFF + 128 * 64)
#define WT_ROOT_OFF (WT_REL_OFF + 4 * 128 * 128)
__device__ float g_wt[WT_ROOT_OFF + 4 * 128 * 128];

// ------------------------- f32x2 helpers -------------------------
__device__ __forceinline__ u64 pk2(float a, float b) {
    u64 r; asm("mov.b64 %0, {%1, %2};" : "=l"(r) : "f"(a), "f"(b)); return r;
}
__device__ __forceinline__ void upk2(u64 v, float& a, float& b) {
    asm("mov.b64 {%0, %1}, %2;" : "=f"(a), "=f"(b) : "l"(v));
}
__device__ __forceinline__ u64 fma2(u64 a, u64 b, u64 c) {
    u64 d; asm("fma.rn.f32x2 %0, %1, %2, %3;" : "=l"(d) : "l"(a), "l"(b), "l"(c)); return d;
}
__device__ __forceinline__ u64 relu2(u64 v) {
    float a, b; upk2(v, a, b);
    return pk2(fmaxf(a, 0.f), fmaxf(b, 0.f));
}

// ------------------------- tf32 mma.sync GEMM (M=128, 512 thr, 2-stage) ---------
__device__ __forceinline__ void mma16n8k8(float* c, const uint32_t* a, const uint32_t* b) {
    asm volatile(
        "mma.sync.aligned.m16n8k8.row.col.f32.tf32.tf32.f32 "
        "{%0,%1,%2,%3}, {%4,%5,%6,%7}, {%8,%9}, {%0,%1,%2,%3};"
        : "+f"(c[0]), "+f"(c[1]), "+f"(c[2]), "+f"(c[3])
        : "r"(a[0]), "r"(a[1]), "r"(a[2]), "r"(a[3]), "r"(b[0]), "r"(b[1]));
}
__device__ __forceinline__ uint32_t smem_u32(const void* p) {
    uint32_t a;
    asm("{ .reg .u64 t; cvta.to.shared.u64 t, %1; cvt.u32.u64 %0, t; }" : "=r"(a) : "l"(p));
    return a;
}
__device__ __forceinline__ void cp16(uint32_t dst, const void* src, int sz) {
    asm volatile("cp.async.ca.shared.global [%0], [%1], 16, %2;" :: "r"(dst), "l"(src), "r"(sz));
}
#define CP_COMMIT() asm volatile("cp.async.commit_group;" ::: "memory")
#define CP_WAIT1()  asm volatile("cp.async.wait_group 1;" ::: "memory")
#define CP_WAIT0()  asm volatile("cp.async.wait_group 0;" ::: "memory")

#define TPITCH 36
#define ATILE  (128 * TPITCH)
#define STAGEW (2 * ATILE)
#define GEMM_SMEM_BYTES (2 * STAGEW * 4)   // 73728 B -> 2 CTAs/SM

__global__ void __launch_bounds__(512) gemm_mma_k(
    const float* __restrict__ A1, const float* __restrict__ B1t, int K1,
    const float* __restrict__ A2, const float* __restrict__ B2t, int K2,
    const float* __restrict__ bias, const float* __restrict__ prev,
    float* __restrict__ C, int M)
{
    extern __shared__ uint32_t sm[];
    const int tid  = threadIdx.x;
    const int lane = tid & 31;
    const int warp = tid >> 5;
    const int wm   = warp & 3;
    const int wn   = warp >> 2;
    const int g    = lane >> 2;
    const int tg   = lane & 3;
    const int m0   = blockIdx.x * 128;
    const uint32_t sbase = smem_u32(sm);

    float acc[2][4][4];
    #pragma unroll
    for (int mf = 0; mf < 2; mf++)
        #pragma unroll
        for (int nf = 0; nf < 4; nf++)
            #pragma unroll
            for (int i = 0; i < 4; i++) acc[mf][nf][i] = 0.f;

    const int nch1 = K1 >> 5;
    const int nch2 = K2 >> 5;
    const int total = nch1 + nch2;

    auto issue_loads = [&](int ch, int stage) {
        const float* A; const float* B; int K, k0;
        if (ch < nch1) { A = A1; B = B1t; K = K1; k0 = ch << 5; }
        else           { A = A2; B = B2t; K = K2; k0 = (ch - nch1) << 5; }
        uint32_t abase = sbase + stage * STAGEW * 4;
        uint32_t bbase = abase + ATILE * 4;
        #pragma unroll
        for (int i = 0; i < 2; i++) {
            int idx = i * 512 + tid;
            int r = idx >> 3, c4 = idx & 7;
            int sz = (m0 + r < M) ? 16 : 0;
            cp16(abase + (r * TPITCH + c4 * 4) * 4,
                 &A[(size_t)(m0 + r < M ? m0 + r : 0) * K + k0 + c4 * 4], sz);
        }
        #pragma unroll
        for (int i = 0; i < 2; i++) {
            int idx = i * 512 + tid;
            int r = idx >> 3, c4 = idx & 7;
            cp16(bbase + (r * TPITCH + c4 * 4) * 4,
                 &B[(size_t)r * K + k0 + c4 * 4], 16);
        }
        CP_COMMIT();
    };

    issue_loads(0, 0);

    for (int ch = 0; ch < total; ch++) {
        const int stage = ch & 1;
        if (ch + 1 < total) {
            issue_loads(ch + 1, stage ^ 1);
            CP_WAIT1();
        } else {
            CP_WAIT0();
        }
        __syncthreads();

        const uint32_t* As = sm + stage * STAGEW;
        const uint32_t* Bs = As + ATILE;

        #pragma unroll
        for (int s = 0; s < 4; s++) {
            const int kk = s * 8;
            uint32_t a[2][4], b[4][2];
            #pragma unroll
            for (int mf = 0; mf < 2; mf++) {
                int rb = wm * 32 + mf * 16;
                a[mf][0] = As[(rb + g    ) * TPITCH + kk + tg    ];
                a[mf][1] = As[(rb + 8 + g) * TPITCH + kk + tg    ];
                a[mf][2] = As[(rb + g    ) * TPITCH + kk + tg + 4];
                a[mf][3] = As[(rb + 8 + g) * TPITCH + kk + tg + 4];
            }
            #pragma unroll
            for (int nf = 0; nf < 4; nf++) {
                int cb = wn * 32 + nf * 8;
                b[nf][0] = Bs[(cb + g) * TPITCH + kk + tg    ];
                b[nf][1] = Bs[(cb + g) * TPITCH + kk + tg + 4];
            }
            #pragma unroll
            for (int mf = 0; mf < 2; mf++)
                #pragma unroll
                for (int nf = 0; nf < 4; nf++)
                    mma16n8k8(acc[mf][nf], a[mf], b[nf]);
        }
        __syncthreads();
    }

    #pragma unroll
    for (int nf = 0; nf < 4; nf++) {
        int col = wn * 32 + nf * 8 + tg * 2;
        float b0 = __ldg(&bias[col]);
        float b1 = __ldg(&bias[col + 1]);
        #pragma unroll
        for (int mf = 0; mf < 2; mf++) {
            int row0 = m0 + wm * 32 + mf * 16 + g;
            if (row0 < M) {
                float2 o;
                o.x = fmaxf(acc[mf][nf][0] + b0, 0.f);
                o.y = fmaxf(acc[mf][nf][1] + b1, 0.f);
                if (prev) {
                    float2 p = *(const float2*)&prev[(size_t)row0 * 128 + col];
                    o.x += p.x; o.y += p.y;
                }
                *(float2*)&C[(size_t)row0 * 128 + col] = o;
            }
            int row1 = row0 + 8;
            if (row1 < M) {
                float2 o;
                o.x = fmaxf(acc[mf][nf][2] + b0, 0.f);
                o.y = fmaxf(acc[mf][nf][3] + b1, 0.f);
                if (prev) {
                    float2 p = *(const float2*)&prev[(size_t)row1 * 128 + col];
                    o.x += p.x; o.y += p.y;
                }
                *(float2*)&C[(size_t)row1 * 128 + col] = o;
            }
        }
    }
}

// ------------------------- transpose + zero all counters (fused) -----------------
__global__ void transpose_zero_k(const float* __restrict__ W_in_fact,
                                 const float* __restrict__ W_in_comp,
                                 const float* __restrict__ W_rel,
                                 const float* __restrict__ W_root,
                                 float* __restrict__ wt,
                                 int* __restrict__ cnt_c, int* __restrict__ cnt_f,
                                 float* __restrict__ pool, float* __restrict__ pcnt)
{
    int i = blockIdx.x * 256 + threadIdx.x;   // grid 512 -> 131072 threads
    int total0 = 384 * 128;
    int total1 = 64 * 128;
    int total2 = 4 * 128 * 128;
    if (i < total0) {
        int k = i >> 7, n = i & 127;
        wt[WT_INF_OFF + n * 384 + k] = W_in_fact[i];
    }
    if (i < total1) {
        int k = i >> 7, n = i & 127;
        wt[WT_INC_OFF + n * 64 + k] = W_in_comp[i];
    }
    if (i < total2) {
        int m = i / 16384, r = i % 16384;
        int k = r >> 7, n = r & 127;
        wt[WT_REL_OFF  + m * 16384 + n * 128 + k] = W_rel[i];
        wt[WT_ROOT_OFF + m * 16384 + n * 128 + k] = W_root[i];
    }
    if (i < NCOMP) cnt_c[i] = 0;
    if (i < NFACT) cnt_f[i] = 0;
    if (i < NBATCH * 256) pool[i] = 0.f;
    if (i < 2 * NBATCH) pcnt[i] = 0.f;
}

// ------------------------- edge gate MLP (f32x2, 2 edges/thread) + hist ----------
__global__ void __launch_bounds__(256) edge_gate_k(
    const float* __restrict__ ea,
    const int* __restrict__ dst, int* __restrict__ cnt,
    const float* __restrict__ eW1, const float* __restrict__ eb1,
    const float* __restrict__ eW2, const float* __restrict__ eb2,
    const float* __restrict__ eW3, const float* __restrict__ eb3,
    float* __restrict__ w)
{
    __shared__ u64 sW1p[11 * 32], sW2p[32 * 16], sW3p[16];
    __shared__ u64 sb1p[32], sb2p[16];
    __shared__ float sb3;
    int tid = threadIdx.x;
    for (int i = tid; i < 11 * 32; i += 256) { float v = eW1[i]; sW1p[i] = pk2(v, v); }
    for (int i = tid; i < 32 * 16; i += 256) { float v = eW2[i]; sW2p[i] = pk2(v, v); }
    if (tid < 32) { float v = eb1[tid]; sb1p[tid] = pk2(v, v); }
    if (tid < 16) {
        float v = eb2[tid]; sb2p[tid] = pk2(v, v);
        float u = eW3[tid]; sW3p[tid] = pk2(u, u);
    }
    if (tid == 0) sb3 = eb3[0];
    __syncthreads();

    int t = blockIdx.x * 256 + tid;
    if (t * 2 >= NE) return;

    atomicAdd(&cnt[__ldg(&dst[t * 2])], 1);
    atomicAdd(&cnt[__ldg(&dst[t * 2 + 1])], 1);

    float4 v4 = *(const float4*)&ea[(size_t)t * 4];

    u64 xx[11];
    {
        float feat[2][11];
        #pragma unroll
        for (int h = 0; h < 2; h++) {
            float sent  = fminf(fmaxf(h ? v4.z : v4.x, -1.f), 1.f);
            float decay = h ? v4.w : v4.y;
            float dt = fmaxf(-__logf(fmaxf(decay, 1e-6f)) * 100.0f, 0.f);
            float ds = fminf(fmaxf(dt * (1.f / 30.f), 0.f), 12.f);
            float s1, c1;
            sincosf(ds, &s1, &c1);
            float s2 = 2.f * s1 * c1;
            float c2 = 1.f - 2.f * s1 * s1;
            float s3 = s1 * c2 + c1 * s2;
            float c3 = c1 * c2 - s1 * s2;
            float s4 = 2.f * s2 * c2;
            float c4 = 1.f - 2.f * s2 * s2;
            feat[h][0] = sent;
            feat[h][1] = __logf(1.f + dt);
            feat[h][2] = s1; feat[h][3] = s2; feat[h][4] = s3; feat[h][5] = s4;
            feat[h][6] = c1; feat[h][7] = c2; feat[h][8] = c3; feat[h][9] = c4;
            feat[h][10] = ds;
        }
        #pragma unroll
        for (int i = 0; i < 11; i++) xx[i] = pk2(feat[0][i], feat[1][i]);
    }

    u64 h1[32];
    #pragma unroll
    for (int j = 0; j < 32; j++) h1[j] = sb1p[j];
    #pragma unroll
    for (int i = 0; i < 11; i++)
        #pragma unroll
        for (int j = 0; j < 32; j++)
            h1[j] = fma2(xx[i], sW1p[i * 32 + j], h1[j]);
    #pragma unroll
    for (int j = 0; j < 32; j++) h1[j] = relu2(h1[j]);

    u64 zp = pk2(sb3, sb3);
    #pragma unroll
    for (int j = 0; j < 16; j++) {
        u64 a = sb2p[j];
        #pragma unroll
        for (int i = 0; i < 32; i++)
            a = fma2(h1[i], sW2p[i * 16 + j], a);
        zp = fma2(relu2(a), sW3p[j], zp);
    }
    float z0, z1;
    upk2(zp, z0, z1);
    float2 o;
    o.x = 1.f / (1.f + __expf(-z0));
    o.y = 1.f / (1.f + __expf(-z1));
    *(float2*)&w[(size_t)t * 2] = o;
}

// ------------------------- CSR build -------------------------
__global__ void scan_block_k(const int* __restrict__ in, int* __restrict__ out,
                             int* __restrict__ bsums, int n)
{
    __shared__ int s[1024];
    int tid = threadIdx.x;
    int i = blockIdx.x * 1024 + tid;
    int v = (i < n) ? in[i] : 0;
    s[tid] = v;
    __syncthreads();
    for (int o = 1; o < 1024; o <<= 1) {
        int t = 0;
        if (tid >= o) t = s[tid - o];
        __syncthreads();
        if (tid >= o) s[tid] += t;
        __syncthreads();
    }
    if (i < n) out[i] = s[tid] - v;
    if (tid == 1023) bsums[blockIdx.x] = s[1023];
}

// adds block-prefix computed inline from bsums (warp 0 reduces bsums[0..bid))
__global__ void scan_add2_k(int* __restrict__ off, int* __restrict__ cur,
                            const int* __restrict__ bsums, int n, int total)
{
    __shared__ int spfx;
    int tid = threadIdx.x;
    int bid = blockIdx.x;
    if (tid < 32) {
        int p = 0;
        for (int j = tid; j < bid; j += 32) p += bsums[j];
        #pragma unroll
        for (int o = 16; o > 0; o >>= 1) p += __shfl_xor_sync(0xffffffffu, p, o);
        if (tid == 0) spfx = p;
    }
    __syncthreads();
    int pfx = spfx;
    int i = bid * 1024 + tid;
    if (i < n) {
        int v = off[i] + pfx;
        off[i] = v;
        cur[i] = v;
    }
    if (i == 0) off[n] = total;
}

__global__ void scatter_k(const int* __restrict__ src, const int* __restrict__ dst,
                          const float* __restrict__ w, int* __restrict__ cur,
                          int* __restrict__ srcs_s, float* __restrict__ ws_s, int n)
{
    int e = blockIdx.x * blockDim.x + threadIdx.x;
    if (e >= n) return;
    int d = dst[e];
    int p = atomicAdd(&cur[d], 1);
    srcs_s[p] = src[e];
    ws_s[p]   = w[e];
}

// ------------------------- gather-side aggregation -------------------------
__global__ void aggregate_k(const int* __restrict__ off, const int* __restrict__ srcs,
                            const float* __restrict__ ws, const float* __restrict__ x,
                            float* __restrict__ out, int n)
{
    int node = blockIdx.x * 2 + (threadIdx.x >> 7);
    int c = threadIdx.x & 127;
    if (node >= n) return;
    int s = off[node], e = off[node + 1];
    float acc = 0.f;
    int i = s;
    for (; i + 4 <= e; i += 4) {
        int s0 = __ldg(&srcs[i]);     int s1 = __ldg(&srcs[i + 1]);
        int s2 = __ldg(&srcs[i + 2]); int s3 = __ldg(&srcs[i + 3]);
        float w0 = __ldg(&ws[i]);     float w1 = __ldg(&ws[i + 1]);
        float w2 = __ldg(&ws[i + 2]); float w3 = __ldg(&ws[i + 3]);
        float x0 = __ldg(&x[(size_t)s0 * 128 + c]);
        float x1 = __ldg(&x[(size_t)s1 * 128 + c]);
        float x2 = __ldg(&x[(size_t)s2 * 128 + c]);
        float x3 = __ldg(&x[(size_t)s3 * 128 + c]);
        acc += x0 * w0 + x1 * w1 + x2 * w2 + x3 * w3;
    }
    for (; i < e; i++)
        acc += __ldg(&x[(size_t)__ldg(&srcs[i]) * 128 + c]) * __ldg(&ws[i]);
    out[(size_t)node * 128 + c] = acc;
}

// ------------------------- layernorm (8 rows/block, 1 warp/row) -------------------------
__global__ void layernorm_k(float* __restrict__ x, const float* __restrict__ scale,
                            const float* __restrict__ bias, int n)
{
    int warp = threadIdx.x >> 5;
    int lane = threadIdx.x & 31;
    int row = blockIdx.x * 8 + warp;
    if (row >= n) return;
    float4 v = *(const float4*)&x[(size_t)row * 128 + lane * 4];
    float s  = v.x + v.y + v.z + v.w;
    float s2 = v.x * v.x + v.y * v.y + v.z * v.z + v.w * v.w;
    #pragma unroll
    for (int o = 16; o > 0; o >>= 1) {
        s  += __shfl_xor_sync(0xffffffffu, s, o);
        s2 += __shfl_xor_sync(0xffffffffu, s2, o);
    }
    float mu  = s * (1.f / 128.f);
    float var = s2 * (1.f / 128.f) - mu * mu;
    float inv = rsqrtf(var + 1e-5f);
    float4 sc = *(const float4*)&scale[lane * 4];
    float4 bi = *(const float4*)&bias[lane * 4];
    float4 o;
    o.x = (v.x - mu) * inv * sc.x + bi.x;
    o.y = (v.y - mu) * inv * sc.y + bi.y;
    o.z = (v.z - mu) * inv * sc.z + bi.z;
    o.w = (v.w - mu) * inv * sc.w + bi.w;
    *(float4*)&x[(size_t)row * 128 + lane * 4] = o;
}

// ------------------------- pooling: fact + comp in one launch --------------------
#define PROWS 64
#define NBF_POOL ((NFACT + PROWS - 1) / PROWS)
#define NBC_POOL ((NCOMP + PROWS - 1) / PROWS)
__global__ void pool_both_k(const float* __restrict__ xf, const int* __restrict__ fbatch,
                            const float* __restrict__ xc, const int* __restrict__ cbatch,
                            float* __restrict__ pool, float* __restrict__ pcnt)
{
    int c = threadIdx.x;
    const float* x; const int* batch; int n, coloff, cntoff, blk;
    if (blockIdx.x < NBF_POOL) {
        x = xf; batch = fbatch; n = NFACT; coloff = 0; cntoff = 0; blk = blockIdx.x;
    } else {
        x = xc; batch = cbatch; n = NCOMP; coloff = 128; cntoff = NBATCH;
        blk = blockIdx.x - NBF_POOL;
    }
    int r0 = blk * PROWS;
    int r1 = r0 + PROWS < n ? r0 + PROWS : n;
    if (r0 >= n) return;
    int curb = __ldg(&batch[r0]);
    float acc = 0.f, cnt = 0.f;
    for (int r = r0; r < r1; r++) {
        int b = __ldg(&batch[r]);
        if (b != curb) {
            atomicAdd(&pool[curb * 256 + coloff + c], acc);
            if (c == 0) atomicAdd(&pcnt[cntoff + curb], cnt);
            acc = 0.f; cnt = 0.f; curb = b;
        }
        acc += x[(size_t)r * 128 + c];
        cnt += 1.f;
    }
    atomicAdd(&pool[curb * 256 + coloff + c], acc);
    if (c == 0) atomicAdd(&pcnt[cntoff + curb], cnt);
}

// ------------------------- classifier (pmean fused) -------------------------
__global__ void classifier_k(const float* __restrict__ pool, const float* __restrict__ pcnt,
                             const float* __restrict__ Wc1, const float* __restrict__ bc1,
                             const float* __restrict__ Wc2, const float* __restrict__ bc2,
                             float* __restrict__ out)
{
    __shared__ float h[64][129];
    __shared__ float invf[64], invc[64];
    int c = threadIdx.x;
    if (c < 64) {
        invf[c] = 1.f / fmaxf(pcnt[c], 1.f);
        invc[c] = 1.f / fmaxf(pcnt[NBATCH + c], 1.f);
    }
    __syncthreads();
    for (int b = 0; b < 64; b++) {
        float a = bc1[c];
        float if_ = invf[b], ic_ = invc[b];
        #pragma unroll 4
        for (int k = 0; k < 128; k++) a += pool[b * 256 + k] * if_ * Wc1[k * 128 + c];
        #pragma unroll 4
        for (int k = 128; k < 256; k++) a += pool[b * 256 + k] * ic_ * Wc1[k * 128 + c];
        h[b][c] = fmaxf(a, 0.f);
    }
    __syncthreads();
    if (c < 64) {
        float a = bc2[0];
        #pragma unroll 4
        for (int k = 0; k < 128; k++) a += h[c][k] * Wc2[k];
        out[c] = a;
    }
}

// ------------------------- host orchestration -------------------------
extern "C" void kernel_launch(void* const* d_in, const int* in_sizes, int n_in,
                              void* d_out, int out_size)
{
    const float* x_fact     = (const float*)d_in[0];
    const float* x_comp     = (const float*)d_in[1];
    const float* ea_f2c     = (const float*)d_in[2];
    const float* ea_c2f     = (const float*)d_in[3];
    const int*   ei_f2c_src = (const int*)d_in[4];
    const int*   ei_f2c_dst = (const int*)d_in[5];
    const int*   ei_c2f_src = (const int*)d_in[6];
    const int*   ei_c2f_dst = (const int*)d_in[7];
    const int*   fact_batch = (const int*)d_in[8];
    const int*   comp_batch = (const int*)d_in[9];
    const float* W_in_fact  = (const float*)d_in[10];
    const float* b_in_fact  = (const float*)d_in[11];
    const float* W_in_comp  = (const float*)d_in[12];
    const float* b_in_comp  = (const float*)d_in[13];
    const float* eW1 = (const float*)d_in[14];
    const float* eb1 = (const float*)d_in[15];
    const float* eW2 = (const float*)d_in[16];
    const float* eb2 = (const float*)d_in[17];
    const float* eW3 = (const float*)d_in[18];
    const float* eb3 = (const float*)d_in[19];
    const float* W_rel    = (const float*)d_in[20];
    const float* b_rel    = (const float*)d_in[21];
    const float* W_root   = (const float*)d_in[22];
    const float* ln_scale = (const float*)d_in[23];
    const float* ln_bias  = (const float*)d_in[24];
    const float* Wc1 = (const float*)d_in[25];
    const float* bc1 = (const float*)d_in[26];
    const float* Wc2 = (const float*)d_in[27];
    const float* bc2 = (const float*)d_in[28];
    float* out = (float*)d_out;

    float *xf, *xf2, *aggf, *xc, *xc2, *aggc, *wf2c, *wc2f;
    float *ws_f2c, *ws_c2f, *pool, *pcnt, *wt;
    int *srcs_f2c, *srcs_c2f, *off_c, *off_f, *cur_c, *cur_f, *cnt_c, *cnt_f;
    int *bsums, *bsums2;
    cudaGetSymbolAddress((void**)&xf,   g_xf);
    cudaGetSymbolAddress((void**)&xf2,  g_xf2);
    cudaGetSymbolAddress((void**)&aggf, g_aggf);
    cudaGetSymbolAddress((void**)&xc,   g_xc);
    cudaGetSymbolAddress((void**)&xc2,  g_xc2);
    cudaGetSymbolAddress((void**)&aggc, g_aggc);
    cudaGetSymbolAddress((void**)&wf2c, g_wf2c);
    cudaGetSymbolAddress((void**)&wc2f, g_wc2f);
    cudaGetSymbolAddress((void**)&srcs_f2c, g_srcs_f2c);
    cudaGetSymbolAddress((void**)&ws_f2c,   g_ws_f2c);
    cudaGetSymbolAddress((void**)&srcs_c2f, g_srcs_c2f);
    cudaGetSymbolAddress((void**)&ws_c2f,   g_ws_c2f);
    cudaGetSymbolAddress((void**)&off_c, g_off_c);
    cudaGetSymbolAddress((void**)&off_f, g_off_f);
    cudaGetSymbolAddress((void**)&cur_c, g_cur_c);
    cudaGetSymbolAddress((void**)&cur_f, g_cur_f);
    cudaGetSymbolAddress((void**)&cnt_c, g_cnt_c);
    cudaGetSymbolAddress((void**)&cnt_f, g_cnt_f);
    cudaGetSymbolAddress((void**)&bsums,  g_bsums);
    cudaGetSymbolAddress((void**)&bsums2, g_bsums2);
    cudaGetSymbolAddress((void**)&pool,  g_pool);
    cudaGetSymbolAddress((void**)&pcnt,  g_pcnt);
    cudaGetSymbolAddress((void**)&wt,    g_wt);

    static cudaStream_t sA = nullptr, sB = nullptr;
    static cudaEvent_t ev[8];
    static int init_done = 0;
    if (!init_done) {
        cudaFuncSetAttribute(gemm_mma_k, cudaFuncAttributeMaxDynamicSharedMemorySize,
                             GEMM_SMEM_BYTES);
        cudaStreamCreateWithFlags(&sA, cudaStreamNonBlocking);
        cudaStreamCreateWithFlags(&sB, cudaStreamNonBlocking);
        for (int i = 0; i < 8; i++) cudaEventCreateWithFlags(&ev[i], cudaEventDisableTiming);
        init_done = 1;
    }

    const int EB = (NE + 255) / 256;
    const int EB2 = (NE / 2 + 255) / 256;
    const int GF = (NFACT + 127) / 128;
    const int GC = (NCOMP + 127) / 128;
    const int nbc = (NCOMP + 1023) / 1024;
    const int nbf = (NFACT + 1023) / 1024;

    // #1 origin: fused transpose + zero-all
    transpose_zero_k<<<512, 256>>>(W_in_fact, W_in_comp, W_rel, W_root, wt,
                                   cnt_c, cnt_f, pool, pcnt);

    // fork after zeroing (gates bump cnt atomically)
    cudaEventRecord(ev[0], 0);
    cudaStreamWaitEvent(sA, ev[0], 0);
    cudaStreamWaitEvent(sB, ev[0], 0);

    // #2 sA, #3 sB: fused gate+hist
    edge_gate_k<<<EB2, 256, 0, sA>>>(ea_f2c, ei_f2c_dst, cnt_c, eW1, eb1, eW2, eb2, eW3, eb3, wf2c);
    edge_gate_k<<<EB2, 256, 0, sB>>>(ea_c2f, ei_c2f_dst, cnt_f, eW1, eb1, eW2, eb2, eW3, eb3, wc2f);
    // #4 origin: fact input GEMM (profiled)
    gemm_mma_k<<<GF, 512, GEMM_SMEM_BYTES>>>(x_fact, wt + WT_INF_OFF, DFACT,
                                             nullptr, nullptr, 0,
                                             b_in_fact, nullptr, xf, NFACT);

    // sA: f2c CSR (dst = comp)
    scan_block_k<<<nbc, 1024, 0, sA>>>(cnt_c, off_c, bsums, NCOMP);
    scan_add2_k<<<nbc, 1024, 0, sA>>>(off_c, cur_c, bsums, NCOMP, NE);
    scatter_k<<<EB, 256, 0, sA>>>(ei_f2c_src, ei_f2c_dst, wf2c, cur_c, srcs_f2c, ws_f2c, NE);
    cudaEventRecord(ev[1], sA);

    // sB: c2f CSR (dst = fact)
    scan_block_k<<<nbf, 1024, 0, sB>>>(cnt_f, off_f, bsums2, NFACT);
    scan_add2_k<<<nbf, 1024, 0, sB>>>(off_f, cur_f, bsums2, NFACT, NE);
    scatter_k<<<EB, 256, 0, sB>>>(ei_c2f_src, ei_c2f_dst, wc2f, cur_f, srcs_c2f, ws_c2f, NE);
    cudaEventRecord(ev[2], sB);

    // origin: comp input GEMM
    gemm_mma_k<<<GC, 512, GEMM_SMEM_BYTES>>>(x_comp, wt + WT_INC_OFF, DCOMP,
                                             nullptr, nullptr, 0,
                                             b_in_comp, nullptr, xc, NCOMP);

    cudaStreamWaitEvent(0, ev[1], 0);
    cudaStreamWaitEvent(0, ev[2], 0);

    float* cf = xf;  float* cc = xc;
    float* nf = xf2; float* nc = xc2;
    for (int l = 0; l < 2; l++) {
        cudaEventRecord(ev[3], 0);
        cudaStreamWaitEvent(sA, ev[3], 0);

        aggregate_k<<<(NCOMP + 1) / 2, 256, 0, sA>>>(off_c, srcs_f2c, ws_f2c, cf, aggc, NCOMP);
        gemm_mma_k<<<GC, 512, GEMM_SMEM_BYTES, sA>>>(aggc, wt + WT_REL_OFF  + (l * 2 + 0) * 16384, 128,
                                                     cc,   wt + WT_ROOT_OFF + (l * 2 + 0) * 16384, 128,
                                                     b_rel + (l * 2 + 0) * 128, cc, nc, NCOMP);
        layernorm_k<<<(NCOMP + 7) / 8, 256, 0, sA>>>(nc, ln_scale + 128, ln_bias + 128, NCOMP);
        cudaEventRecord(ev[4], sA);

        aggregate_k<<<(NFACT + 1) / 2, 256>>>(off_f, srcs_c2f, ws_c2f, cc, aggf, NFACT);
        gemm_mma_k<<<GF, 512, GEMM_SMEM_BYTES>>>(aggf, wt + WT_REL_OFF  + (l * 2 + 1) * 16384, 128,
                                                 cf,   wt + WT_ROOT_OFF + (l * 2 + 1) * 16384, 128,
                                                 b_rel + (l * 2 + 1) * 128, cf, nf, NFACT);
        layernorm_k<<<(NFACT + 7) / 8, 256>>>(nf, ln_scale, ln_bias, NFACT);

        cudaStreamWaitEvent(0, ev[4], 0);

        float* t;
        t = cf; cf = nf; nf = t;
        t = cc; cc = nc; nc = t;
    }

    // pools fused into one launch, then classifier
    pool_both_k<<<NBF_POOL + NBC_POOL, 128>>>(cf, fact_batch, cc, comp_batch, pool, pcnt);
    classifier_k<<<1, 128>>>(pool, pcnt, Wc1, bc1, Wc2, bc2, out);
}

// round 16
// speedup vs baseline: 1.1349x; 1.0821x over previous
#include <cuda_runtime.h>
#include <math.h>
#include <stdint.h>

#define H128 128
#define NFACT 100000
#define NCOMP 5000
#define NE 500000
#define NBATCH 64
#define DFACT 384
#define DCOMP 64

typedef unsigned long long u64;

// ------------------------- static scratch (device .bss) -------------------------
__device__ float g_xf  [NFACT * H128];
__device__ float g_xf2 [NFACT * H128];
__device__ float g_aggf[NFACT * H128];
__device__ float g_xc  [NCOMP * H128];
__device__ float g_xc2 [NCOMP * H128];
__device__ float g_aggc[NCOMP * H128];
__device__ float g_wf2c[NE];
__device__ float g_wc2f[NE];
__device__ int   g_srcs_f2c[NE];
__device__ float g_ws_f2c  [NE];
__device__ int   g_srcs_c2f[NE];
__device__ float g_ws_c2f  [NE];
__device__ int   g_off_c[NCOMP + 1];
__device__ int   g_off_f[NFACT + 1];
__device__ int   g_cur_c[NCOMP];
__device__ int   g_cur_f[NFACT];
__device__ int   g_cnt_c[NCOMP];
__device__ int   g_cnt_f[NFACT];
__device__ int   g_bsums [256];
__device__ int   g_bsums2[256];
__device__ float g_pool [NBATCH * 256];
__device__ float g_pcnt [2 * NBATCH];
// transposed weights
#define WT_INF_OFF  0
#define WT_INC_OFF  (128 * 384)
#define WT_REL_OFF  (WT_INC_OFF + 128 * 64)
#define WT_ROOT_OFF (WT_REL_OFF + 4 * 128 * 128)
__device__ float g_wt[WT_ROOT_OFF + 4 * 128 * 128];

// ------------------------- f32x2 helpers -------------------------
__device__ __forceinline__ u64 pk2(float a, float b) {
    u64 r; asm("mov.b64 %0, {%1, %2};" : "=l"(r) : "f"(a), "f"(b)); return r;
}
__device__ __forceinline__ void upk2(u64 v, float& a, float& b) {
    asm("mov.b64 {%0, %1}, %2;" : "=f"(a), "=f"(b) : "l"(v));
}
__device__ __forceinline__ u64 fma2(u64 a, u64 b, u64 c) {
    u64 d; asm("fma.rn.f32x2 %0, %1, %2, %3;" : "=l"(d) : "l"(a), "l"(b), "l"(c)); return d;
}
__device__ __forceinline__ u64 relu2(u64 v) {
    float a, b; upk2(v, a, b);
    return pk2(fmaxf(a, 0.f), fmaxf(b, 0.f));
}

// ------------------------- tf32 mma.sync GEMM (M=128, 512 thr, 2-stage) ---------
__device__ __forceinline__ void mma16n8k8(float* c, const uint32_t* a, const uint32_t* b) {
    asm volatile(
        "mma.sync.aligned.m16n8k8.row.col.f32.tf32.tf32.f32 "
        "{%0,%1,%2,%3}, {%4,%5,%6,%7}, {%8,%9}, {%0,%1,%2,%3};"
        : "+f"(c[0]), "+f"(c[1]), "+f"(c[2]), "+f"(c[3])
        : "r"(a[0]), "r"(a[1]), "r"(a[2]), "r"(a[3]), "r"(b[0]), "r"(b[1]));
}
__device__ __forceinline__ uint32_t smem_u32(const void* p) {
    uint32_t a;
    asm("{ .reg .u64 t; cvta.to.shared.u64 t, %1; cvt.u32.u64 %0, t; }" : "=r"(a) : "l"(p));
    return a;
}
__device__ __forceinline__ void cp16(uint32_t dst, const void* src, int sz) {
    asm volatile("cp.async.ca.shared.global [%0], [%1], 16, %2;" :: "r"(dst), "l"(src), "r"(sz));
}
#define CP_COMMIT() asm volatile("cp.async.commit_group;" ::: "memory")
#define CP_WAIT1()  asm volatile("cp.async.wait_group 1;" ::: "memory")
#define CP_WAIT0()  asm volatile("cp.async.wait_group 0;" ::: "memory")

#define TPITCH 36
#define ATILE  (128 * TPITCH)
#define STAGEW (2 * ATILE)
#define GEMM_SMEM_BYTES (2 * STAGEW * 4)   // 73728 B -> 2 CTAs/SM

__global__ void __launch_bounds__(512) gemm_mma_k(
    const float* __restrict__ A1, const float* __restrict__ B1t, int K1,
    const float* __restrict__ A2, const float* __restrict__ B2t, int K2,
    const float* __restrict__ bias, const float* __restrict__ prev,
    float* __restrict__ C, int M)
{
    extern __shared__ uint32_t sm[];
    const int tid  = threadIdx.x;
    const int lane = tid & 31;
    const int warp = tid >> 5;
    const int wm   = warp & 3;
    const int wn   = warp >> 2;
    const int g    = lane >> 2;
    const int tg   = lane & 3;
    const int m0   = blockIdx.x * 128;
    const uint32_t sbase = smem_u32(sm);

    float acc[2][4][4];
    #pragma unroll
    for (int mf = 0; mf < 2; mf++)
        #pragma unroll
        for (int nf = 0; nf < 4; nf++)
            #pragma unroll
            for (int i = 0; i < 4; i++) acc[mf][nf][i] = 0.f;

    const int nch1 = K1 >> 5;
    const int nch2 = K2 >> 5;
    const int total = nch1 + nch2;

    auto issue_loads = [&](int ch, int stage) {
        const float* A; const float* B; int K, k0;
        if (ch < nch1) { A = A1; B = B1t; K = K1; k0 = ch << 5; }
        else           { A = A2; B = B2t; K = K2; k0 = (ch - nch1) << 5; }
        uint32_t abase = sbase + stage * STAGEW * 4;
        uint32_t bbase = abase + ATILE * 4;
        #pragma unroll
        for (int i = 0; i < 2; i++) {
            int idx = i * 512 + tid;
            int r = idx >> 3, c4 = idx & 7;
            int sz = (m0 + r < M) ? 16 : 0;
            cp16(abase + (r * TPITCH + c4 * 4) * 4,
                 &A[(size_t)(m0 + r < M ? m0 + r : 0) * K + k0 + c4 * 4], sz);
        }
        #pragma unroll
        for (int i = 0; i < 2; i++) {
            int idx = i * 512 + tid;
            int r = idx >> 3, c4 = idx & 7;
            cp16(bbase + (r * TPITCH + c4 * 4) * 4,
                 &B[(size_t)r * K + k0 + c4 * 4], 16);
        }
        CP_COMMIT();
    };

    issue_loads(0, 0);

    for (int ch = 0; ch < total; ch++) {
        const int stage = ch & 1;
        if (ch + 1 < total) {
            issue_loads(ch + 1, stage ^ 1);
            CP_WAIT1();
        } else {
            CP_WAIT0();
        }
        __syncthreads();

        const uint32_t* As = sm + stage * STAGEW;
        const uint32_t* Bs = As + ATILE;

        #pragma unroll
        for (int s = 0; s < 4; s++) {
            const int kk = s * 8;
            uint32_t a[2][4], b[4][2];
            #pragma unroll
            for (int mf = 0; mf < 2; mf++) {
                int rb = wm * 32 + mf * 16;
                a[mf][0] = As[(rb + g    ) * TPITCH + kk + tg    ];
                a[mf][1] = As[(rb + 8 + g) * TPITCH + kk + tg    ];
                a[mf][2] = As[(rb + g    ) * TPITCH + kk + tg + 4];
                a[mf][3] = As[(rb + 8 + g) * TPITCH + kk + tg + 4];
            }
            #pragma unroll
            for (int nf = 0; nf < 4; nf++) {
                int cb = wn * 32 + nf * 8;
                b[nf][0] = Bs[(cb + g) * TPITCH + kk + tg    ];
                b[nf][1] = Bs[(cb + g) * TPITCH + kk + tg + 4];
            }
            #pragma unroll
            for (int mf = 0; mf < 2; mf++)
                #pragma unroll
                for (int nf = 0; nf < 4; nf++)
                    mma16n8k8(acc[mf][nf], a[mf], b[nf]);
        }
        __syncthreads();
    }

    #pragma unroll
    for (int nf = 0; nf < 4; nf++) {
        int col = wn * 32 + nf * 8 + tg * 2;
        float b0 = __ldg(&bias[col]);
        float b1 = __ldg(&bias[col + 1]);
        #pragma unroll
        for (int mf = 0; mf < 2; mf++) {
            int row0 = m0 + wm * 32 + mf * 16 + g;
            if (row0 < M) {
                float2 o;
                o.x = fmaxf(acc[mf][nf][0] + b0, 0.f);
                o.y = fmaxf(acc[mf][nf][1] + b1, 0.f);
                if (prev) {
                    float2 p = *(const float2*)&prev[(size_t)row0 * 128 + col];
                    o.x += p.x; o.y += p.y;
                }
                *(float2*)&C[(size_t)row0 * 128 + col] = o;
            }
            int row1 = row0 + 8;
            if (row1 < M) {
                float2 o;
                o.x = fmaxf(acc[mf][nf][2] + b0, 0.f);
                o.y = fmaxf(acc[mf][nf][3] + b1, 0.f);
                if (prev) {
                    float2 p = *(const float2*)&prev[(size_t)row1 * 128 + col];
                    o.x += p.x; o.y += p.y;
                }
                *(float2*)&C[(size_t)row1 * 128 + col] = o;
            }
        }
    }
}

// ------------------------- transpose + zero all counters (fused) -----------------
__global__ void transpose_zero_k(const float* __restrict__ W_in_fact,
                                 const float* __restrict__ W_in_comp,
                                 const float* __restrict__ W_rel,
                                 const float* __restrict__ W_root,
                                 float* __restrict__ wt,
                                 int* __restrict__ cnt_c, int* __restrict__ cnt_f,
                                 float* __restrict__ pool, float* __restrict__ pcnt)
{
    int i = blockIdx.x * 256 + threadIdx.x;
    int total0 = 384 * 128;
    int total1 = 64 * 128;
    int total2 = 4 * 128 * 128;
    if (i < total0) {
        int k = i >> 7, n = i & 127;
        wt[WT_INF_OFF + n * 384 + k] = W_in_fact[i];
    }
    if (i < total1) {
        int k = i >> 7, n = i & 127;
        wt[WT_INC_OFF + n * 64 + k] = W_in_comp[i];
    }
    if (i < total2) {
        int m = i / 16384, r = i % 16384;
        int k = r >> 7, n = r & 127;
        wt[WT_REL_OFF  + m * 16384 + n * 128 + k] = W_rel[i];
        wt[WT_ROOT_OFF + m * 16384 + n * 128 + k] = W_root[i];
    }
    if (i < NCOMP) cnt_c[i] = 0;
    if (i < NFACT) cnt_f[i] = 0;
    if (i < NBATCH * 256) pool[i] = 0.f;
    if (i < 2 * NBATCH) pcnt[i] = 0.f;
}

// ------------------------- edge gate MLP (f32x2, 2 edges/thread) + hist ----------
__global__ void __launch_bounds__(256) edge_gate_k(
    const float* __restrict__ ea,
    const int* __restrict__ dst, int* __restrict__ cnt,
    const float* __restrict__ eW1, const float* __restrict__ eb1,
    const float* __restrict__ eW2, const float* __restrict__ eb2,
    const float* __restrict__ eW3, const float* __restrict__ eb3,
    float* __restrict__ w)
{
    __shared__ u64 sW1p[11 * 32], sW2p[32 * 16], sW3p[16];
    __shared__ u64 sb1p[32], sb2p[16];
    __shared__ float sb3;
    int tid = threadIdx.x;
    for (int i = tid; i < 11 * 32; i += 256) { float v = eW1[i]; sW1p[i] = pk2(v, v); }
    for (int i = tid; i < 32 * 16; i += 256) { float v = eW2[i]; sW2p[i] = pk2(v, v); }
    if (tid < 32) { float v = eb1[tid]; sb1p[tid] = pk2(v, v); }
    if (tid < 16) {
        float v = eb2[tid]; sb2p[tid] = pk2(v, v);
        float u = eW3[tid]; sW3p[tid] = pk2(u, u);
    }
    if (tid == 0) sb3 = eb3[0];
    __syncthreads();

    int t = blockIdx.x * 256 + tid;
    if (t * 2 >= NE) return;

    atomicAdd(&cnt[__ldg(&dst[t * 2])], 1);
    atomicAdd(&cnt[__ldg(&dst[t * 2 + 1])], 1);

    float4 v4 = *(const float4*)&ea[(size_t)t * 4];

    u64 xx[11];
    {
        float feat[2][11];
        #pragma unroll
        for (int h = 0; h < 2; h++) {
            float sent  = fminf(fmaxf(h ? v4.z : v4.x, -1.f), 1.f);
            float decay = h ? v4.w : v4.y;
            float dt = fmaxf(-__logf(fmaxf(decay, 1e-6f)) * 100.0f, 0.f);
            float ds = fminf(fmaxf(dt * (1.f / 30.f), 0.f), 12.f);
            float s1, c1;
            sincosf(ds, &s1, &c1);
            float s2 = 2.f * s1 * c1;
            float c2 = 1.f - 2.f * s1 * s1;
            float s3 = s1 * c2 + c1 * s2;
            float c3 = c1 * c2 - s1 * s2;
            float s4 = 2.f * s2 * c2;
            float c4 = 1.f - 2.f * s2 * s2;
            feat[h][0] = sent;
            feat[h][1] = __logf(1.f + dt);
            feat[h][2] = s1; feat[h][3] = s2; feat[h][4] = s3; feat[h][5] = s4;
            feat[h][6] = c1; feat[h][7] = c2; feat[h][8] = c3; feat[h][9] = c4;
            feat[h][10] = ds;
        }
        #pragma unroll
        for (int i = 0; i < 11; i++) xx[i] = pk2(feat[0][i], feat[1][i]);
    }

    u64 h1[32];
    #pragma unroll
    for (int j = 0; j < 32; j++) h1[j] = sb1p[j];
    #pragma unroll
    for (int i = 0; i < 11; i++)
        #pragma unroll
        for (int j = 0; j < 32; j++)
            h1[j] = fma2(xx[i], sW1p[i * 32 + j], h1[j]);
    #pragma unroll
    for (int j = 0; j < 32; j++) h1[j] = relu2(h1[j]);

    u64 zp = pk2(sb3, sb3);
    #pragma unroll
    for (int j = 0; j < 16; j++) {
        u64 a = sb2p[j];
        #pragma unroll
        for (int i = 0; i < 32; i++)
            a = fma2(h1[i], sW2p[i * 16 + j], a);
        zp = fma2(relu2(a), sW3p[j], zp);
    }
    float z0, z1;
    upk2(zp, z0, z1);
    float2 o;
    o.x = 1.f / (1.f + __expf(-z0));
    o.y = 1.f / (1.f + __expf(-z1));
    *(float2*)&w[(size_t)t * 2] = o;
}

// ------------------------- CSR build -------------------------
__global__ void scan_block_k(const int* __restrict__ in, int* __restrict__ out,
                             int* __restrict__ bsums, int n)
{
    __shared__ int s[1024];
    int tid = threadIdx.x;
    int i = blockIdx.x * 1024 + tid;
    int v = (i < n) ? in[i] : 0;
    s[tid] = v;
    __syncthreads();
    for (int o = 1; o < 1024; o <<= 1) {
        int t = 0;
        if (tid >= o) t = s[tid - o];
        __syncthreads();
        if (tid >= o) s[tid] += t;
        __syncthreads();
    }
    if (i < n) out[i] = s[tid] - v;
    if (tid == 1023) bsums[blockIdx.x] = s[1023];
}

__global__ void scan_add2_k(int* __restrict__ off, int* __restrict__ cur,
                            const int* __restrict__ bsums, int n, int total)
{
    __shared__ int spfx;
    int tid = threadIdx.x;
    int bid = blockIdx.x;
    if (tid < 32) {
        int p = 0;
        for (int j = tid; j < bid; j += 32) p += bsums[j];
        #pragma unroll
        for (int o = 16; o > 0; o >>= 1) p += __shfl_xor_sync(0xffffffffu, p, o);
        if (tid == 0) spfx = p;
    }
    __syncthreads();
    int pfx = spfx;
    int i = bid * 1024 + tid;
    if (i < n) {
        int v = off[i] + pfx;
        off[i] = v;
        cur[i] = v;
    }
    if (i == 0) off[n] = total;
}

__global__ void scatter_k(const int* __restrict__ src, const int* __restrict__ dst,
                          const float* __restrict__ w, int* __restrict__ cur,
                          int* __restrict__ srcs_s, float* __restrict__ ws_s, int n)
{
    int e = blockIdx.x * blockDim.x + threadIdx.x;
    if (e >= n) return;
    int d = dst[e];
    int p = atomicAdd(&cur[d], 1);
    srcs_s[p] = src[e];
    ws_s[p]   = w[e];
}

// ------------------------- gather aggregation: warp-per-node, float4 lanes -------
__global__ void __launch_bounds__(256) aggregate_k(
    const int* __restrict__ off, const int* __restrict__ srcs,
    const float* __restrict__ ws, const float* __restrict__ x,
    float* __restrict__ out, int n)
{
    int warp = threadIdx.x >> 5;               // 8 warps per block
    int lane = threadIdx.x & 31;               // lane covers channels 4*lane..4*lane+3
    int node = blockIdx.x * 8 + warp;
    if (node >= n) return;
    int s = off[node], e = off[node + 1];
    float4 acc = make_float4(0.f, 0.f, 0.f, 0.f);
    int i = s;
    for (; i + 2 <= e; i += 2) {
        int   s0 = __ldg(&srcs[i]);     int   s1 = __ldg(&srcs[i + 1]);
        float w0 = __ldg(&ws[i]);       float w1 = __ldg(&ws[i + 1]);
        float4 x0 = *(const float4*)&x[(size_t)s0 * 128 + lane * 4];
        float4 x1 = *(const float4*)&x[(size_t)s1 * 128 + lane * 4];
        acc.x += x0.x * w0 + x1.x * w1;
        acc.y += x0.y * w0 + x1.y * w1;
        acc.z += x0.z * w0 + x1.z * w1;
        acc.w += x0.w * w0 + x1.w * w1;
    }
    if (i < e) {
        int   s0 = __ldg(&srcs[i]);
        float w0 = __ldg(&ws[i]);
        float4 x0 = *(const float4*)&x[(size_t)s0 * 128 + lane * 4];
        acc.x += x0.x * w0; acc.y += x0.y * w0;
        acc.z += x0.z * w0; acc.w += x0.w * w0;
    }
    *(float4*)&out[(size_t)node * 128 + lane * 4] = acc;
}

// ------------------------- layernorm (8 rows/block, 1 warp/row) -------------------------
__global__ void layernorm_k(float* __restrict__ x, const float* __restrict__ scale,
                            const float* __restrict__ bias, int n)
{
    int warp = threadIdx.x >> 5;
    int lane = threadIdx.x & 31;
    int row = blockIdx.x * 8 + warp;
    if (row >= n) return;
    float4 v = *(const float4*)&x[(size_t)row * 128 + lane * 4];
    float s  = v.x + v.y + v.z + v.w;
    float s2 = v.x * v.x + v.y * v.y + v.z * v.z + v.w * v.w;
    #pragma unroll
    for (int o = 16; o > 0; o >>= 1) {
        s  += __shfl_xor_sync(0xffffffffu, s, o);
        s2 += __shfl_xor_sync(0xffffffffu, s2, o);
    }
    float mu  = s * (1.f / 128.f);
    float var = s2 * (1.f / 128.f) - mu * mu;
    float inv = rsqrtf(var + 1e-5f);
    float4 sc = *(const float4*)&scale[lane * 4];
    float4 bi = *(const float4*)&bias[lane * 4];
    float4 o;
    o.x = (v.x - mu) * inv * sc.x + bi.x;
    o.y = (v.y - mu) * inv * sc.y + bi.y;
    o.z = (v.z - mu) * inv * sc.z + bi.z;
    o.w = (v.w - mu) * inv * sc.w + bi.w;
    *(float4*)&x[(size_t)row * 128 + lane * 4] = o;
}

// ------------------------- pooling: fact + comp in one launch --------------------
#define PROWS 64
#define NBF_POOL ((NFACT + PROWS - 1) / PROWS)
#define NBC_POOL ((NCOMP + PROWS - 1) / PROWS)
__global__ void pool_both_k(const float* __restrict__ xf, const int* __restrict__ fbatch,
                            const float* __restrict__ xc, const int* __restrict__ cbatch,
                            float* __restrict__ pool, float* __restrict__ pcnt)
{
    int c = threadIdx.x;
    const float* x; const int* batch; int n, coloff, cntoff, blk;
    if (blockIdx.x < NBF_POOL) {
        x = xf; batch = fbatch; n = NFACT; coloff = 0; cntoff = 0; blk = blockIdx.x;
    } else {
        x = xc; batch = cbatch; n = NCOMP; coloff = 128; cntoff = NBATCH;
        blk = blockIdx.x - NBF_POOL;
    }
    int r0 = blk * PROWS;
    int r1 = r0 + PROWS < n ? r0 + PROWS : n;
    if (r0 >= n) return;
    int curb = __ldg(&batch[r0]);
    float acc = 0.f, cnt = 0.f;
    for (int r = r0; r < r1; r++) {
        int b = __ldg(&batch[r]);
        if (b != curb) {
            atomicAdd(&pool[curb * 256 + coloff + c], acc);
            if (c == 0) atomicAdd(&pcnt[cntoff + curb], cnt);
            acc = 0.f; cnt = 0.f; curb = b;
        }
        acc += x[(size_t)r * 128 + c];
        cnt += 1.f;
    }
    atomicAdd(&pool[curb * 256 + coloff + c], acc);
    if (c == 0) atomicAdd(&pcnt[cntoff + curb], cnt);
}

// ------------------------- classifier (pmean fused) -------------------------
__global__ void classifier_k(const float* __restrict__ pool, const float* __restrict__ pcnt,
                             const float* __restrict__ Wc1, const float* __restrict__ bc1,
                             const float* __restrict__ Wc2, const float* __restrict__ bc2,
                             float* __restrict__ out)
{
    __shared__ float h[64][129];
    __shared__ float invf[64], invc[64];
    int c = threadIdx.x;
    if (c < 64) {
        invf[c] = 1.f / fmaxf(pcnt[c], 1.f);
        invc[c] = 1.f / fmaxf(pcnt[NBATCH + c], 1.f);
    }
    __syncthreads();
    for (int b = 0; b < 64; b++) {
        float a = bc1[c];
        float if_ = invf[b], ic_ = invc[b];
        #pragma unroll 4
        for (int k = 0; k < 128; k++) a += pool[b * 256 + k] * if_ * Wc1[k * 128 + c];
        #pragma unroll 4
        for (int k = 128; k < 256; k++) a += pool[b * 256 + k] * ic_ * Wc1[k * 128 + c];
        h[b][c] = fmaxf(a, 0.f);
    }
    __syncthreads();
    if (c < 64) {
        float a = bc2[0];
        #pragma unroll 4
        for (int k = 0; k < 128; k++) a += h[c][k] * Wc2[k];
        out[c] = a;
    }
}

// ------------------------- host orchestration -------------------------
extern "C" void kernel_launch(void* const* d_in, const int* in_sizes, int n_in,
                              void* d_out, int out_size)
{
    const float* x_fact     = (const float*)d_in[0];
    const float* x_comp     = (const float*)d_in[1];
    const float* ea_f2c     = (const float*)d_in[2];
    const float* ea_c2f     = (const float*)d_in[3];
    const int*   ei_f2c_src = (const int*)d_in[4];
    const int*   ei_f2c_dst = (const int*)d_in[5];
    const int*   ei_c2f_src = (const int*)d_in[6];
    const int*   ei_c2f_dst = (const int*)d_in[7];
    const int*   fact_batch = (const int*)d_in[8];
    const int*   comp_batch = (const int*)d_in[9];
    const float* W_in_fact  = (const float*)d_in[10];
    const float* b_in_fact  = (const float*)d_in[11];
    const float* W_in_comp  = (const float*)d_in[12];
    const float* b_in_comp  = (const float*)d_in[13];
    const float* eW1 = (const float*)d_in[14];
    const float* eb1 = (const float*)d_in[15];
    const float* eW2 = (const float*)d_in[16];
    const float* eb2 = (const float*)d_in[17];
    const float* eW3 = (const float*)d_in[18];
    const float* eb3 = (const float*)d_in[19];
    const float* W_rel    = (const float*)d_in[20];
    const float* b_rel    = (const float*)d_in[21];
    const float* W_root   = (const float*)d_in[22];
    const float* ln_scale = (const float*)d_in[23];
    const float* ln_bias  = (const float*)d_in[24];
    const float* Wc1 = (const float*)d_in[25];
    const float* bc1 = (const float*)d_in[26];
    const float* Wc2 = (const float*)d_in[27];
    const float* bc2 = (const float*)d_in[28];
    float* out = (float*)d_out;

    float *xf, *xf2, *aggf, *xc, *xc2, *aggc, *wf2c, *wc2f;
    float *ws_f2c, *ws_c2f, *pool, *pcnt, *wt;
    int *srcs_f2c, *srcs_c2f, *off_c, *off_f, *cur_c, *cur_f, *cnt_c, *cnt_f;
    int *bsums, *bsums2;
    cudaGetSymbolAddress((void**)&xf,   g_xf);
    cudaGetSymbolAddress((void**)&xf2,  g_xf2);
    cudaGetSymbolAddress((void**)&aggf, g_aggf);
    cudaGetSymbolAddress((void**)&xc,   g_xc);
    cudaGetSymbolAddress((void**)&xc2,  g_xc2);
    cudaGetSymbolAddress((void**)&aggc, g_aggc);
    cudaGetSymbolAddress((void**)&wf2c, g_wf2c);
    cudaGetSymbolAddress((void**)&wc2f, g_wc2f);
    cudaGetSymbolAddress((void**)&srcs_f2c, g_srcs_f2c);
    cudaGetSymbolAddress((void**)&ws_f2c,   g_ws_f2c);
    cudaGetSymbolAddress((void**)&srcs_c2f, g_srcs_c2f);
    cudaGetSymbolAddress((void**)&ws_c2f,   g_ws_c2f);
    cudaGetSymbolAddress((void**)&off_c, g_off_c);
    cudaGetSymbolAddress((void**)&off_f, g_off_f);
    cudaGetSymbolAddress((void**)&cur_c, g_cur_c);
    cudaGetSymbolAddress((void**)&cur_f, g_cur_f);
    cudaGetSymbolAddress((void**)&cnt_c, g_cnt_c);
    cudaGetSymbolAddress((void**)&cnt_f, g_cnt_f);
    cudaGetSymbolAddress((void**)&bsums,  g_bsums);
    cudaGetSymbolAddress((void**)&bsums2, g_bsums2);
    cudaGetSymbolAddress((void**)&pool,  g_pool);
    cudaGetSymbolAddress((void**)&pcnt,  g_pcnt);
    cudaGetSymbolAddress((void**)&wt,    g_wt);

    static cudaStream_t sA = nullptr, sB = nullptr;
    static cudaEvent_t ev[8];
    static int init_done = 0;
    if (!init_done) {
        cudaFuncSetAttribute(gemm_mma_k, cudaFuncAttributeMaxDynamicSharedMemorySize,
                             GEMM_SMEM_BYTES);
        cudaStreamCreateWithFlags(&sA, cudaStreamNonBlocking);
        cudaStreamCreateWithFlags(&sB, cudaStreamNonBlocking);
        for (int i = 0; i < 8; i++) cudaEventCreateWithFlags(&ev[i], cudaEventDisableTiming);
        init_done = 1;
    }

    const int EB = (NE + 255) / 256;
    const int EB2 = (NE / 2 + 255) / 256;
    const int GF = (NFACT + 127) / 128;
    const int GC = (NCOMP + 127) / 128;
    const int nbc = (NCOMP + 1023) / 1024;
    const int nbf = (NFACT + 1023) / 1024;

    // #1 origin: fused transpose + zero-all
    transpose_zero_k<<<512, 256>>>(W_in_fact, W_in_comp, W_rel, W_root, wt,
                                   cnt_c, cnt_f, pool, pcnt);

    cudaEventRecord(ev[0], 0);
    cudaStreamWaitEvent(sA, ev[0], 0);
    cudaStreamWaitEvent(sB, ev[0], 0);

    // #2 sA, #3 sB: fused gate+hist
    edge_gate_k<<<EB2, 256, 0, sA>>>(ea_f2c, ei_f2c_dst, cnt_c, eW1, eb1, eW2, eb2, eW3, eb3, wf2c);
    edge_gate_k<<<EB2, 256, 0, sB>>>(ea_c2f, ei_c2f_dst, cnt_f, eW1, eb1, eW2, eb2, eW3, eb3, wc2f);
    // #4 origin: fact input GEMM (profiled)
    gemm_mma_k<<<GF, 512, GEMM_SMEM_BYTES>>>(x_fact, wt + WT_INF_OFF, DFACT,
                                             nullptr, nullptr, 0,
                                             b_in_fact, nullptr, xf, NFACT);

    // sA: f2c CSR (dst = comp)
    scan_block_k<<<nbc, 1024, 0, sA>>>(cnt_c, off_c, bsums, NCOMP);
    scan_add2_k<<<nbc, 1024, 0, sA>>>(off_c, cur_c, bsums, NCOMP, NE);
    scatter_k<<<EB, 256, 0, sA>>>(ei_f2c_src, ei_f2c_dst, wf2c, cur_c, srcs_f2c, ws_f2c, NE);
    cudaEventRecord(ev[1], sA);

    // sB: c2f CSR (dst = fact)
    scan_block_k<<<nbf, 1024, 0, sB>>>(cnt_f, off_f, bsums2, NFACT);
    scan_add2_k<<<nbf, 1024, 0, sB>>>(off_f, cur_f, bsums2, NFACT, NE);
    scatter_k<<<EB, 256, 0, sB>>>(ei_c2f_src, ei_c2f_dst, wc2f, cur_f, srcs_c2f, ws_c2f, NE);
    cudaEventRecord(ev[2], sB);

    // origin: comp input GEMM
    gemm_mma_k<<<GC, 512, GEMM_SMEM_BYTES>>>(x_comp, wt + WT_INC_OFF, DCOMP,
                                             nullptr, nullptr, 0,
                                             b_in_comp, nullptr, xc, NCOMP);

    cudaStreamWaitEvent(0, ev[1], 0);
    cudaStreamWaitEvent(0, ev[2], 0);

    float* cf = xf;  float* cc = xc;
    float* nf = xf2; float* nc = xc2;
    for (int l = 0; l < 2; l++) {
        cudaEventRecord(ev[3], 0);
        cudaStreamWaitEvent(sA, ev[3], 0);

        aggregate_k<<<(NCOMP + 7) / 8, 256, 0, sA>>>(off_c, srcs_f2c, ws_f2c, cf, aggc, NCOMP);
        gemm_mma_k<<<GC, 512, GEMM_SMEM_BYTES, sA>>>(aggc, wt + WT_REL_OFF  + (l * 2 + 0) * 16384, 128,
                                                     cc,   wt + WT_ROOT_OFF + (l * 2 + 0) * 16384, 128,
                                                     b_rel + (l * 2 + 0) * 128, cc, nc, NCOMP);
        layernorm_k<<<(NCOMP + 7) / 8, 256, 0, sA>>>(nc, ln_scale + 128, ln_bias + 128, NCOMP);
        cudaEventRecord(ev[4], sA);

        aggregate_k<<<(NFACT + 7) / 8, 256>>>(off_f, srcs_c2f, ws_c2f, cc, aggf, NFACT);
        gemm_mma_k<<<GF, 512, GEMM_SMEM_BYTES>>>(aggf, wt + WT_REL_OFF  + (l * 2 + 1) * 16384, 128,
                                                 cf,   wt + WT_ROOT_OFF + (l * 2 + 1) * 16384, 128,
                                                 b_rel + (l * 2 + 1) * 128, cf, nf, NFACT);
        layernorm_k<<<(NFACT + 7) / 8, 256>>>(nf, ln_scale, ln_bias, NFACT);

        cudaStreamWaitEvent(0, ev[4], 0);

        float* t;
        t = cf; cf = nf; nf = t;
        t = cc; cc = nc; nc = t;
    }

    pool_both_k<<<NBF_POOL + NBC_POOL, 128>>>(cf, fact_batch, cc, comp_batch, pool, pcnt);
    classifier_k<<<1, 128>>>(pool, pcnt, Wc1, bc1, Wc2, bc2, out);
}

// round 17
// speedup vs baseline: 1.1385x; 1.0032x over previous
#include <cuda_runtime.h>
#include <math.h>
#include <stdint.h>

#define H128 128
#define NFACT 100000
#define NCOMP 5000
#define NE 500000
#define NBATCH 64
#define DFACT 384
#define DCOMP 64

typedef unsigned long long u64;

// ------------------------- static scratch (device .bss) -------------------------
__device__ float g_xf  [NFACT * H128];
__device__ float g_xf2 [NFACT * H128];
__device__ float g_aggf[NFACT * H128];
__device__ float g_xc  [NCOMP * H128];
__device__ float g_xc2 [NCOMP * H128];
__device__ float g_aggc[NCOMP * H128];
__device__ float g_wf2c[NE];
__device__ float g_wc2f[NE];
__device__ int2  g_edge_f2c[NE];
__device__ int2  g_edge_c2f[NE];
__device__ int   g_off_c[NCOMP + 1];
__device__ int   g_off_f[NFACT + 1];
__device__ int   g_cur_c[NCOMP];
__device__ int   g_cur_f[NFACT];
__device__ int   g_cnt_c[NCOMP];
__device__ int   g_cnt_f[NFACT];
__device__ int   g_bsums [256];
__device__ int   g_bsums2[256];
__device__ float g_pool [NBATCH * 256];
__device__ float g_pcnt [2 * NBATCH];
// transposed weights
#define WT_INF_OFF  0
#define WT_INC_OFF  (128 * 384)
#define WT_REL_OFF  (WT_INC_OFF + 128 * 64)
#define WT_ROOT_OFF (WT_REL_OFF + 4 * 128 * 128)
__device__ float g_wt[WT_ROOT_OFF + 4 * 128 * 128];

// ------------------------- f32x2 helpers -------------------------
__device__ __forceinline__ u64 pk2(float a, float b) {
    u64 r; asm("mov.b64 %0, {%1, %2};" : "=l"(r) : "f"(a), "f"(b)); return r;
}
__device__ __forceinline__ void upk2(u64 v, float& a, float& b) {
    asm("mov.b64 {%0, %1}, %2;" : "=f"(a), "=f"(b) : "l"(v));
}
__device__ __forceinline__ u64 fma2(u64 a, u64 b, u64 c) {
    u64 d; asm("fma.rn.f32x2 %0, %1, %2, %3;" : "=l"(d) : "l"(a), "l"(b), "l"(c)); return d;
}
__device__ __forceinline__ u64 relu2(u64 v) {
    float a, b; upk2(v, a, b);
    return pk2(fmaxf(a, 0.f), fmaxf(b, 0.f));
}

// ------------------------- tf32 mma.sync GEMM (M=128, 512 thr, 2-stage) ---------
__device__ __forceinline__ void mma16n8k8(float* c, const uint32_t* a, const uint32_t* b) {
    asm volatile(
        "mma.sync.aligned.m16n8k8.row.col.f32.tf32.tf32.f32 "
        "{%0,%1,%2,%3}, {%4,%5,%6,%7}, {%8,%9}, {%0,%1,%2,%3};"
        : "+f"(c[0]), "+f"(c[1]), "+f"(c[2]), "+f"(c[3])
        : "r"(a[0]), "r"(a[1]), "r"(a[2]), "r"(a[3]), "r"(b[0]), "r"(b[1]));
}
__device__ __forceinline__ uint32_t smem_u32(const void* p) {
    uint32_t a;
    asm("{ .reg .u64 t; cvta.to.shared.u64 t, %1; cvt.u32.u64 %0, t; }" : "=r"(a) : "l"(p));
    return a;
}
__device__ __forceinline__ void cp16(uint32_t dst, const void* src, int sz) {
    asm volatile("cp.async.ca.shared.global [%0], [%1], 16, %2;" :: "r"(dst), "l"(src), "r"(sz));
}
#define CP_COMMIT() asm volatile("cp.async.commit_group;" ::: "memory")
#define CP_WAIT1()  asm volatile("cp.async.wait_group 1;" ::: "memory")
#define CP_WAIT0()  asm volatile("cp.async.wait_group 0;" ::: "memory")

#define TPITCH 36
#define ATILE  (128 * TPITCH)
#define STAGEW (2 * ATILE)
#define GEMM_SMEM_BYTES (2 * STAGEW * 4)   // 73728 B -> 2 CTAs/SM

__global__ void __launch_bounds__(512) gemm_mma_k(
    const float* __restrict__ A1, const float* __restrict__ B1t, int K1,
    const float* __restrict__ A2, const float* __restrict__ B2t, int K2,
    const float* __restrict__ bias, const float* __restrict__ prev,
    float* __restrict__ C, int M)
{
    extern __shared__ uint32_t sm[];
    const int tid  = threadIdx.x;
    const int lane = tid & 31;
    const int warp = tid >> 5;
    const int wm   = warp & 3;
    const int wn   = warp >> 2;
    const int g    = lane >> 2;
    const int tg   = lane & 3;
    const int m0   = blockIdx.x * 128;
    const uint32_t sbase = smem_u32(sm);

    float acc[2][4][4];
    #pragma unroll
    for (int mf = 0; mf < 2; mf++)
        #pragma unroll
        for (int nf = 0; nf < 4; nf++)
            #pragma unroll
            for (int i = 0; i < 4; i++) acc[mf][nf][i] = 0.f;

    const int nch1 = K1 >> 5;
    const int nch2 = K2 >> 5;
    const int total = nch1 + nch2;

    auto issue_loads = [&](int ch, int stage) {
        const float* A; const float* B; int K, k0;
        if (ch < nch1) { A = A1; B = B1t; K = K1; k0 = ch << 5; }
        else           { A = A2; B = B2t; K = K2; k0 = (ch - nch1) << 5; }
        uint32_t abase = sbase + stage * STAGEW * 4;
        uint32_t bbase = abase + ATILE * 4;
        #pragma unroll
        for (int i = 0; i < 2; i++) {
            int idx = i * 512 + tid;
            int r = idx >> 3, c4 = idx & 7;
            int sz = (m0 + r < M) ? 16 : 0;
            cp16(abase + (r * TPITCH + c4 * 4) * 4,
                 &A[(size_t)(m0 + r < M ? m0 + r : 0) * K + k0 + c4 * 4], sz);
        }
        #pragma unroll
        for (int i = 0; i < 2; i++) {
            int idx = i * 512 + tid;
            int r = idx >> 3, c4 = idx & 7;
            cp16(bbase + (r * TPITCH + c4 * 4) * 4,
                 &B[(size_t)r * K + k0 + c4 * 4], 16);
        }
        CP_COMMIT();
    };

    issue_loads(0, 0);

    for (int ch = 0; ch < total; ch++) {
        const int stage = ch & 1;
        if (ch + 1 < total) {
            issue_loads(ch + 1, stage ^ 1);
            CP_WAIT1();
        } else {
            CP_WAIT0();
        }
        __syncthreads();

        const uint32_t* As = sm + stage * STAGEW;
        const uint32_t* Bs = As + ATILE;

        #pragma unroll
        for (int s = 0; s < 4; s++) {
            const int kk = s * 8;
            uint32_t a[2][4], b[4][2];
            #pragma unroll
            for (int mf = 0; mf < 2; mf++) {
                int rb = wm * 32 + mf * 16;
                a[mf][0] = As[(rb + g    ) * TPITCH + kk + tg    ];
                a[mf][1] = As[(rb + 8 + g) * TPITCH + kk + tg    ];
                a[mf][2] = As[(rb + g    ) * TPITCH + kk + tg + 4];
                a[mf][3] = As[(rb + 8 + g) * TPITCH + kk + tg + 4];
            }
            #pragma unroll
            for (int nf = 0; nf < 4; nf++) {
                int cb = wn * 32 + nf * 8;
                b[nf][0] = Bs[(cb + g) * TPITCH + kk + tg    ];
                b[nf][1] = Bs[(cb + g) * TPITCH + kk + tg + 4];
            }
            #pragma unroll
            for (int mf = 0; mf < 2; mf++)
                #pragma unroll
                for (int nf = 0; nf < 4; nf++)
                    mma16n8k8(acc[mf][nf], a[mf], b[nf]);
        }
        __syncthreads();
    }

    #pragma unroll
    for (int nf = 0; nf < 4; nf++) {
        int col = wn * 32 + nf * 8 + tg * 2;
        float b0 = __ldg(&bias[col]);
        float b1 = __ldg(&bias[col + 1]);
        #pragma unroll
        for (int mf = 0; mf < 2; mf++) {
            int row0 = m0 + wm * 32 + mf * 16 + g;
            if (row0 < M) {
                float2 o;
                o.x = fmaxf(acc[mf][nf][0] + b0, 0.f);
                o.y = fmaxf(acc[mf][nf][1] + b1, 0.f);
                if (prev) {
                    float2 p = *(const float2*)&prev[(size_t)row0 * 128 + col];
                    o.x += p.x; o.y += p.y;
                }
                *(float2*)&C[(size_t)row0 * 128 + col] = o;
            }
            int row1 = row0 + 8;
            if (row1 < M) {
                float2 o;
                o.x = fmaxf(acc[mf][nf][2] + b0, 0.f);
                o.y = fmaxf(acc[mf][nf][3] + b1, 0.f);
                if (prev) {
                    float2 p = *(const float2*)&prev[(size_t)row1 * 128 + col];
                    o.x += p.x; o.y += p.y;
                }
                *(float2*)&C[(size_t)row1 * 128 + col] = o;
            }
        }
    }
}

// ------------------------- transpose + zero all counters (fused) -----------------
__global__ void transpose_zero_k(const float* __restrict__ W_in_fact,
                                 const float* __restrict__ W_in_comp,
                                 const float* __restrict__ W_rel,
                                 const float* __restrict__ W_root,
                                 float* __restrict__ wt,
                                 int* __restrict__ cnt_c, int* __restrict__ cnt_f,
                                 float* __restrict__ pool, float* __restrict__ pcnt)
{
    int i = blockIdx.x * 256 + threadIdx.x;
    int total0 = 384 * 128;
    int total1 = 64 * 128;
    int total2 = 4 * 128 * 128;
    if (i < total0) {
        int k = i >> 7, n = i & 127;
        wt[WT_INF_OFF + n * 384 + k] = W_in_fact[i];
    }
    if (i < total1) {
        int k = i >> 7, n = i & 127;
        wt[WT_INC_OFF + n * 64 + k] = W_in_comp[i];
    }
    if (i < total2) {
        int m = i / 16384, r = i % 16384;
        int k = r >> 7, n = r & 127;
        wt[WT_REL_OFF  + m * 16384 + n * 128 + k] = W_rel[i];
        wt[WT_ROOT_OFF + m * 16384 + n * 128 + k] = W_root[i];
    }
    if (i < NCOMP) cnt_c[i] = 0;
    if (i < NFACT) cnt_f[i] = 0;
    if (i < NBATCH * 256) pool[i] = 0.f;
    if (i < 2 * NBATCH) pcnt[i] = 0.f;
}

// ------------------------- edge gate MLP (f32x2, 2 edges/thread) + hist ----------
__global__ void __launch_bounds__(256) edge_gate_k(
    const float* __restrict__ ea,
    const int* __restrict__ dst, int* __restrict__ cnt,
    const float* __restrict__ eW1, const float* __restrict__ eb1,
    const float* __restrict__ eW2, const float* __restrict__ eb2,
    const float* __restrict__ eW3, const float* __restrict__ eb3,
    float* __restrict__ w)
{
    __shared__ u64 sW1p[11 * 32], sW2p[32 * 16], sW3p[16];
    __shared__ u64 sb1p[32], sb2p[16];
    __shared__ float sb3;
    int tid = threadIdx.x;
    for (int i = tid; i < 11 * 32; i += 256) { float v = eW1[i]; sW1p[i] = pk2(v, v); }
    for (int i = tid; i < 32 * 16; i += 256) { float v = eW2[i]; sW2p[i] = pk2(v, v); }
    if (tid < 32) { float v = eb1[tid]; sb1p[tid] = pk2(v, v); }
    if (tid < 16) {
        float v = eb2[tid]; sb2p[tid] = pk2(v, v);
        float u = eW3[tid]; sW3p[tid] = pk2(u, u);
    }
    if (tid == 0) sb3 = eb3[0];
    __syncthreads();

    int t = blockIdx.x * 256 + tid;
    if (t * 2 >= NE) return;

    atomicAdd(&cnt[__ldg(&dst[t * 2])], 1);
    atomicAdd(&cnt[__ldg(&dst[t * 2 + 1])], 1);

    float4 v4 = *(const float4*)&ea[(size_t)t * 4];

    u64 xx[11];
    {
        float feat[2][11];
        #pragma unroll
        for (int h = 0; h < 2; h++) {
            float sent  = fminf(fmaxf(h ? v4.z : v4.x, -1.f), 1.f);
            float decay = h ? v4.w : v4.y;
            float dt = fmaxf(-__logf(fmaxf(decay, 1e-6f)) * 100.0f, 0.f);
            float ds = fminf(fmaxf(dt * (1.f / 30.f), 0.f), 12.f);
            float s1, c1;
            sincosf(ds, &s1, &c1);
            float s2 = 2.f * s1 * c1;
            float c2 = 1.f - 2.f * s1 * s1;
            float s3 = s1 * c2 + c1 * s2;
            float c3 = c1 * c2 - s1 * s2;
            float s4 = 2.f * s2 * c2;
            float c4 = 1.f - 2.f * s2 * s2;
            feat[h][0] = sent;
            feat[h][1] = __logf(1.f + dt);
            feat[h][2] = s1; feat[h][3] = s2; feat[h][4] = s3; feat[h][5] = s4;
            feat[h][6] = c1; feat[h][7] = c2; feat[h][8] = c3; feat[h][9] = c4;
            feat[h][10] = ds;
        }
        #pragma unroll
        for (int i = 0; i < 11; i++) xx[i] = pk2(feat[0][i], feat[1][i]);
    }

    u64 h1[32];
    #pragma unroll
    for (int j = 0; j < 32; j++) h1[j] = sb1p[j];
    #pragma unroll
    for (int i = 0; i < 11; i++)
        #pragma unroll
        for (int j = 0; j < 32; j++)
            h1[j] = fma2(xx[i], sW1p[i * 32 + j], h1[j]);
    #pragma unroll
    for (int j = 0; j < 32; j++) h1[j] = relu2(h1[j]);

    u64 zp = pk2(sb3, sb3);
    #pragma unroll
    for (int j = 0; j < 16; j++) {
        u64 a = sb2p[j];
        #pragma unroll
        for (int i = 0; i < 32; i++)
            a = fma2(h1[i], sW2p[i * 16 + j], a);
        zp = fma2(relu2(a), sW3p[j], zp);
    }
    float z0, z1;
    upk2(zp, z0, z1);
    float2 o;
    o.x = 1.f / (1.f + __expf(-z0));
    o.y = 1.f / (1.f + __expf(-z1));
    *(float2*)&w[(size_t)t * 2] = o;
}

// ------------------------- CSR build -------------------------
__global__ void scan_block_k(const int* __restrict__ in, int* __restrict__ out,
                             int* __restrict__ bsums, int n)
{
    __shared__ int s[1024];
    int tid = threadIdx.x;
    int i = blockIdx.x * 1024 + tid;
    int v = (i < n) ? in[i] : 0;
    s[tid] = v;
    __syncthreads();
    for (int o = 1; o < 1024; o <<= 1) {
        int t = 0;
        if (tid >= o) t = s[tid - o];
        __syncthreads();
        if (tid >= o) s[tid] += t;
        __syncthreads();
    }
    if (i < n) out[i] = s[tid] - v;
    if (tid == 1023) bsums[blockIdx.x] = s[1023];
}

__global__ void scan_add2_k(int* __restrict__ off, int* __restrict__ cur,
                            const int* __restrict__ bsums, int n, int total)
{
    __shared__ int spfx;
    int tid = threadIdx.x;
    int bid = blockIdx.x;
    if (tid < 32) {
        int p = 0;
        for (int j = tid; j < bid; j += 32) p += bsums[j];
        #pragma unroll
        for (int o = 16; o > 0; o >>= 1) p += __shfl_xor_sync(0xffffffffu, p, o);
        if (tid == 0) spfx = p;
    }
    __syncthreads();
    int pfx = spfx;
    int i = bid * 1024 + tid;
    if (i < n) {
        int v = off[i] + pfx;
        off[i] = v;
        cur[i] = v;
    }
    if (i == 0) off[n] = total;
}

__global__ void scatter_k(const int* __restrict__ src, const int* __restrict__ dst,
                          const float* __restrict__ w, int* __restrict__ cur,
                          int2* __restrict__ edges, int n)
{
    int e = blockIdx.x * blockDim.x + threadIdx.x;
    if (e >= n) return;
    int d = dst[e];
    int p = atomicAdd(&cur[d], 1);
    edges[p] = make_int2(src[e], __float_as_int(w[e]));
}

// ------------------------- gather aggregation: warp-per-node, float4, unroll 4 ---
__global__ void __launch_bounds__(256) aggregate_k(
    const int* __restrict__ off, const int2* __restrict__ edges,
    const float* __restrict__ x, float* __restrict__ out, int n)
{
    int warp = threadIdx.x >> 5;
    int lane = threadIdx.x & 31;
    int node = blockIdx.x * 8 + warp;
    if (node >= n) return;
    int s = off[node], e = off[node + 1];
    float4 acc = make_float4(0.f, 0.f, 0.f, 0.f);
    int i = s;
    for (; i + 4 <= e; i += 4) {
        int2 e0 = __ldg(&edges[i]);     int2 e1 = __ldg(&edges[i + 1]);
        int2 e2 = __ldg(&edges[i + 2]); int2 e3 = __ldg(&edges[i + 3]);
        float4 x0 = *(const float4*)&x[(size_t)e0.x * 128 + lane * 4];
        float4 x1 = *(const float4*)&x[(size_t)e1.x * 128 + lane * 4];
        float4 x2 = *(const float4*)&x[(size_t)e2.x * 128 + lane * 4];
        float4 x3 = *(const float4*)&x[(size_t)e3.x * 128 + lane * 4];
        float w0 = __int_as_float(e0.y), w1 = __int_as_float(e1.y);
        float w2 = __int_as_float(e2.y), w3 = __int_as_float(e3.y);
        acc.x += x0.x * w0 + x1.x * w1 + x2.x * w2 + x3.x * w3;
        acc.y += x0.y * w0 + x1.y * w1 + x2.y * w2 + x3.y * w3;
        acc.z += x0.z * w0 + x1.z * w1 + x2.z * w2 + x3.z * w3;
        acc.w += x0.w * w0 + x1.w * w1 + x2.w * w2 + x3.w * w3;
    }
    for (; i < e; i++) {
        int2 e0 = __ldg(&edges[i]);
        float w0 = __int_as_float(e0.y);
        float4 x0 = *(const float4*)&x[(size_t)e0.x * 128 + lane * 4];
        acc.x += x0.x * w0; acc.y += x0.y * w0;
        acc.z += x0.z * w0; acc.w += x0.w * w0;
    }
    *(float4*)&out[(size_t)node * 128 + lane * 4] = acc;
}

// ------------------------- layernorm (8 rows/block, 1 warp/row) -------------------------
__global__ void layernorm_k(float* __restrict__ x, const float* __restrict__ scale,
                            const float* __restrict__ bias, int n)
{
    int warp = threadIdx.x >> 5;
    int lane = threadIdx.x & 31;
    int row = blockIdx.x * 8 + warp;
    if (row >= n) return;
    float4 v = *(const float4*)&x[(size_t)row * 128 + lane * 4];
    float s  = v.x + v.y + v.z + v.w;
    float s2 = v.x * v.x + v.y * v.y + v.z * v.z + v.w * v.w;
    #pragma unroll
    for (int o = 16; o > 0; o >>= 1) {
        s  += __shfl_xor_sync(0xffffffffu, s, o);
        s2 += __shfl_xor_sync(0xffffffffu, s2, o);
    }
    float mu  = s * (1.f / 128.f);
    float var = s2 * (1.f / 128.f) - mu * mu;
    float inv = rsqrtf(var + 1e-5f);
    float4 sc = *(const float4*)&scale[lane * 4];
    float4 bi = *(const float4*)&bias[lane * 4];
    float4 o;
    o.x = (v.x - mu) * inv * sc.x + bi.x;
    o.y = (v.y - mu) * inv * sc.y + bi.y;
    o.z = (v.z - mu) * inv * sc.z + bi.z;
    o.w = (v.w - mu) * inv * sc.w + bi.w;
    *(float4*)&x[(size_t)row * 128 + lane * 4] = o;
}

// ------------------------- pooling: fact + comp in one launch --------------------
#define PROWS 64
#define NBF_POOL ((NFACT + PROWS - 1) / PROWS)
#define NBC_POOL ((NCOMP + PROWS - 1) / PROWS)
__global__ void pool_both_k(const float* __restrict__ xf, const int* __restrict__ fbatch,
                            const float* __restrict__ xc, const int* __restrict__ cbatch,
                            float* __restrict__ pool, float* __restrict__ pcnt)
{
    int c = threadIdx.x;
    const float* x; const int* batch; int n, coloff, cntoff, blk;
    if (blockIdx.x < NBF_POOL) {
        x = xf; batch = fbatch; n = NFACT; coloff = 0; cntoff = 0; blk = blockIdx.x;
    } else {
        x = xc; batch = cbatch; n = NCOMP; coloff = 128; cntoff = NBATCH;
        blk = blockIdx.x - NBF_POOL;
    }
    int r0 = blk * PROWS;
    int r1 = r0 + PROWS < n ? r0 + PROWS : n;
    if (r0 >= n) return;
    int curb = __ldg(&batch[r0]);
    float acc = 0.f, cnt = 0.f;
    for (int r = r0; r < r1; r++) {
        int b = __ldg(&batch[r]);
        if (b != curb) {
            atomicAdd(&pool[curb * 256 + coloff + c], acc);
            if (c == 0) atomicAdd(&pcnt[cntoff + curb], cnt);
            acc = 0.f; cnt = 0.f; curb = b;
        }
        acc += x[(size_t)r * 128 + c];
        cnt += 1.f;
    }
    atomicAdd(&pool[curb * 256 + coloff + c], acc);
    if (c == 0) atomicAdd(&pcnt[cntoff + curb], cnt);
}

// ------------------------- classifier (pmean fused) -------------------------
__global__ void classifier_k(const float* __restrict__ pool, const float* __restrict__ pcnt,
                             const float* __restrict__ Wc1, const float* __restrict__ bc1,
                             const float* __restrict__ Wc2, const float* __restrict__ bc2,
                             float* __restrict__ out)
{
    __shared__ float h[64][129];
    __shared__ float invf[64], invc[64];
    int c = threadIdx.x;
    if (c < 64) {
        invf[c] = 1.f / fmaxf(pcnt[c], 1.f);
        invc[c] = 1.f / fmaxf(pcnt[NBATCH + c], 1.f);
    }
    __syncthreads();
    for (int b = 0; b < 64; b++) {
        float a = bc1[c];
        float if_ = invf[b], ic_ = invc[b];
        #pragma unroll 4
        for (int k = 0; k < 128; k++) a += pool[b * 256 + k] * if_ * Wc1[k * 128 + c];
        #pragma unroll 4
        for (int k = 128; k < 256; k++) a += pool[b * 256 + k] * ic_ * Wc1[k * 128 + c];
        h[b][c] = fmaxf(a, 0.f);
    }
    __syncthreads();
    if (c < 64) {
        float a = bc2[0];
        #pragma unroll 4
        for (int k = 0; k < 128; k++) a += h[c][k] * Wc2[k];
        out[c] = a;
    }
}

// ------------------------- host orchestration -------------------------
extern "C" void kernel_launch(void* const* d_in, const int* in_sizes, int n_in,
                              void* d_out, int out_size)
{
    const float* x_fact     = (const float*)d_in[0];
    const float* x_comp     = (const float*)d_in[1];
    const float* ea_f2c     = (const float*)d_in[2];
    const float* ea_c2f     = (const float*)d_in[3];
    const int*   ei_f2c_src = (const int*)d_in[4];
    const int*   ei_f2c_dst = (const int*)d_in[5];
    const int*   ei_c2f_src = (const int*)d_in[6];
    const int*   ei_c2f_dst = (const int*)d_in[7];
    const int*   fact_batch = (const int*)d_in[8];
    const int*   comp_batch = (const int*)d_in[9];
    const float* W_in_fact  = (const float*)d_in[10];
    const float* b_in_fact  = (const float*)d_in[11];
    const float* W_in_comp  = (const float*)d_in[12];
    const float* b_in_comp  = (const float*)d_in[13];
    const float* eW1 = (const float*)d_in[14];
    const float* eb1 = (const float*)d_in[15];
    const float* eW2 = (const float*)d_in[16];
    const float* eb2 = (const float*)d_in[17];
    const float* eW3 = (const float*)d_in[18];
    const float* eb3 = (const float*)d_in[19];
    const float* W_rel    = (const float*)d_in[20];
    const float* b_rel    = (const float*)d_in[21];
    const float* W_root   = (const float*)d_in[22];
    const float* ln_scale = (const float*)d_in[23];
    const float* ln_bias  = (const float*)d_in[24];
    const float* Wc1 = (const float*)d_in[25];
    const float* bc1 = (const float*)d_in[26];
    const float* Wc2 = (const float*)d_in[27];
    const float* bc2 = (const float*)d_in[28];
    float* out = (float*)d_out;

    float *xf, *xf2, *aggf, *xc, *xc2, *aggc, *wf2c, *wc2f;
    float *pool, *pcnt, *wt;
    int2 *edges_f2c, *edges_c2f;
    int *off_c, *off_f, *cur_c, *cur_f, *cnt_c, *cnt_f;
    int *bsums, *bsums2;
    cudaGetSymbolAddress((void**)&xf,   g_xf);
    cudaGetSymbolAddress((void**)&xf2,  g_xf2);
    cudaGetSymbolAddress((void**)&aggf, g_aggf);
    cudaGetSymbolAddress((void**)&xc,   g_xc);
    cudaGetSymbolAddress((void**)&xc2,  g_xc2);
    cudaGetSymbolAddress((void**)&aggc, g_aggc);
    cudaGetSymbolAddress((void**)&wf2c, g_wf2c);
    cudaGetSymbolAddress((void**)&wc2f, g_wc2f);
    cudaGetSymbolAddress((void**)&edges_f2c, g_edge_f2c);
    cudaGetSymbolAddress((void**)&edges_c2f, g_edge_c2f);
    cudaGetSymbolAddress((void**)&off_c, g_off_c);
    cudaGetSymbolAddress((void**)&off_f, g_off_f);
    cudaGetSymbolAddress((void**)&cur_c, g_cur_c);
    cudaGetSymbolAddress((void**)&cur_f, g_cur_f);
    cudaGetSymbolAddress((void**)&cnt_c, g_cnt_c);
    cudaGetSymbolAddress((void**)&cnt_f, g_cnt_f);
    cudaGetSymbolAddress((void**)&bsums,  g_bsums);
    cudaGetSymbolAddress((void**)&bsums2, g_bsums2);
    cudaGetSymbolAddress((void**)&pool,  g_pool);
    cudaGetSymbolAddress((void**)&pcnt,  g_pcnt);
    cudaGetSymbolAddress((void**)&wt,    g_wt);

    static cudaStream_t sA = nullptr, sB = nullptr;
    static cudaEvent_t ev[8];
    static int init_done = 0;
    if (!init_done) {
        cudaFuncSetAttribute(gemm_mma_k, cudaFuncAttributeMaxDynamicSharedMemorySize,
                             GEMM_SMEM_BYTES);
        cudaStreamCreateWithFlags(&sA, cudaStreamNonBlocking);
        cudaStreamCreateWithFlags(&sB, cudaStreamNonBlocking);
        for (int i = 0; i < 8; i++) cudaEventCreateWithFlags(&ev[i], cudaEventDisableTiming);
        init_done = 1;
    }

    const int EB = (NE + 255) / 256;
    const int EB2 = (NE / 2 + 255) / 256;
    const int GF = (NFACT + 127) / 128;
    const int GC = (NCOMP + 127) / 128;
    const int nbc = (NCOMP + 1023) / 1024;
    const int nbf = (NFACT + 1023) / 1024;

    // #1 origin: fused transpose + zero-all
    transpose_zero_k<<<512, 256>>>(W_in_fact, W_in_comp, W_rel, W_root, wt,
                                   cnt_c, cnt_f, pool, pcnt);

    cudaEventRecord(ev[0], 0);
    cudaStreamWaitEvent(sA, ev[0], 0);
    cudaStreamWaitEvent(sB, ev[0], 0);

    // #2 sA, #3 sB: fused gate+hist
    edge_gate_k<<<EB2, 256, 0, sA>>>(ea_f2c, ei_f2c_dst, cnt_c, eW1, eb1, eW2, eb2, eW3, eb3, wf2c);
    edge_gate_k<<<EB2, 256, 0, sB>>>(ea_c2f, ei_c2f_dst, cnt_f, eW1, eb1, eW2, eb2, eW3, eb3, wc2f);
    // #4 origin: fact input GEMM (profiled)
    gemm_mma_k<<<GF, 512, GEMM_SMEM_BYTES>>>(x_fact, wt + WT_INF_OFF, DFACT,
                                             nullptr, nullptr, 0,
                                             b_in_fact, nullptr, xf, NFACT);

    // sA: f2c CSR (dst = comp)
    scan_block_k<<<nbc, 1024, 0, sA>>>(cnt_c, off_c, bsums, NCOMP);
    scan_add2_k<<<nbc, 1024, 0, sA>>>(off_c, cur_c, bsums, NCOMP, NE);
    scatter_k<<<EB, 256, 0, sA>>>(ei_f2c_src, ei_f2c_dst, wf2c, cur_c, edges_f2c, NE);
    cudaEventRecord(ev[1], sA);

    // sB: c2f CSR (dst = fact)
    scan_block_k<<<nbf, 1024, 0, sB>>>(cnt_f, off_f, bsums2, NFACT);
    scan_add2_k<<<nbf, 1024, 0, sB>>>(off_f, cur_f, bsums2, NFACT, NE);
    scatter_k<<<EB, 256, 0, sB>>>(ei_c2f_src, ei_c2f_dst, wc2f, cur_f, edges_c2f, NE);
    cudaEventRecord(ev[2], sB);

    // origin: comp input GEMM
    gemm_mma_k<<<GC, 512, GEMM_SMEM_BYTES>>>(x_comp, wt + WT_INC_OFF, DCOMP,
                                             nullptr, nullptr, 0,
                                             b_in_comp, nullptr, xc, NCOMP);

    cudaStreamWaitEvent(0, ev[1], 0);
    cudaStreamWaitEvent(0, ev[2], 0);

    float* cf = xf;  float* cc = xc;
    float* nf = xf2; float* nc = xc2;
    for (int l = 0; l < 2; l++) {
        cudaEventRecord(ev[3], 0);
        cudaStreamWaitEvent(sA, ev[3], 0);

        aggregate_k<<<(NCOMP + 7) / 8, 256, 0, sA>>>(off_c, edges_f2c, cf, aggc, NCOMP);
        gemm_mma_k<<<GC, 512, GEMM_SMEM_BYTES, sA>>>(aggc, wt + WT_REL_OFF  + (l * 2 + 0) * 16384, 128,
                                                     cc,   wt + WT_ROOT_OFF + (l * 2 + 0) * 16384, 128,
                                                     b_rel + (l * 2 + 0) * 128, cc, nc, NCOMP);
        layernorm_k<<<(NCOMP + 7) / 8, 256, 0, sA>>>(nc, ln_scale + 128, ln_bias + 128, NCOMP);
        cudaEventRecord(ev[4], sA);

        aggregate_k<<<(NFACT + 7) / 8, 256>>>(off_f, edges_c2f, cc, aggf, NFACT);
        gemm_mma_k<<<GF, 512, GEMM_SMEM_BYTES>>>(aggf, wt + WT_REL_OFF  + (l * 2 + 1) * 16384, 128,
                                                 cf,   wt + WT_ROOT_OFF + (l * 2 + 1) * 16384, 128,
                                                 b_rel + (l * 2 + 1) * 128, cf, nf, NFACT);
        layernorm_k<<<(NFACT + 7) / 8, 256>>>(nf, ln_scale, ln_bias, NFACT);

        cudaStreamWaitEvent(0, ev[4], 0);

        float* t;
        t = cf; cf = nf; nf = t;
        t = cc; cc = nc; nc = t;
    }

    pool_both_k<<<NBF_POOL + NBC_POOL, 128>>>(cf, fact_batch, cc, comp_batch, pool, pcnt);
    classifier_k<<<1, 128>>>(pool, pcnt, Wc1, bc1, Wc2, bc2, out);
}